// round 1
// baseline (speedup 1.0000x reference)
#include <cuda_runtime.h>
#include <math.h>

#define NN 8192
#define EE 262144
#define ETOT (EE + NN)
#define DIN 256
#define HID 64

// ---------------- scratch (device globals; no allocation allowed) ----------------
static __device__ float g_S[(size_t)2 * NN * NN];          // 536 MB: per-head scores/probs
static __device__ float g_h1[NN * 128];
static __device__ float g_agg1[NN * 128];
static __device__ float g_ht1[NN * 128];
static __device__ float g_h2[NN * 64];
static __device__ float g_agg2[NN * 64];
static __device__ float g_htkg[NN * 64];
static __device__ float g_as1[NN * 2], g_ad1[NN * 2], g_m1[NN * 2], g_d1[NN * 2];
static __device__ float g_eexp1[ETOT * 2];
static __device__ float g_as2[NN], g_ad2[NN], g_m2[NN], g_d2[NN];
static __device__ float g_eexp2[ETOT];
static __device__ float g_deg[NN], g_dinv[NN];
static __device__ float g_g1[NN * 64], g_agge1[NN * 64], g_he1[NN * 64];
static __device__ float g_g2[NN * 64], g_agge2[NN * 64], g_hekg[NN * 64];
static __device__ float g_q[NN * 64], g_k[NN * 64], g_v[NN * 64];
static __device__ float g_attnout[NN * 64];
static __device__ float g_hattn[NN * 64];
static __device__ float g_fused[NN * 128];
static __device__ float g_t1[NN * 64];

// ---------------- helpers ----------------
__device__ __forceinline__ void atomicMaxF(float* addr, float v) {
    if (v >= 0.f) atomicMax((int*)addr, __float_as_int(v));
    else          atomicMin((unsigned int*)addr, __float_as_uint(v));
}

__global__ void fill_kernel(float* p, float v, int n) {
    int i = blockIdx.x * blockDim.x + threadIdx.x;
    if (i < n) p[i] = v;
}

// ---------------- generic tiled GEMM: C = act(A[M,K] @ B[K,N] + bias) ----------------
// BM=64, BN=64, BK=16, 256 threads, 4x4 per thread. K % 16 == 0, N % 64 == 0, M % 64 == 0.
__global__ __launch_bounds__(256) void gemm64(const float* __restrict__ A,
                                              const float* __restrict__ B,
                                              const float* __restrict__ bias,
                                              float* __restrict__ C,
                                              int M, int N, int K, int act) {
    __shared__ float As[16][65];   // [k][m] padded
    __shared__ float Bs[16][64];   // [k][n]
    int tid = threadIdx.x;
    int tx = tid & 15, ty = tid >> 4;
    int m0 = blockIdx.y * 64, n0 = blockIdx.x * 64;
    float acc[4][4] = {};
    for (int k0 = 0; k0 < K; k0 += 16) {
        {
            int r = tid >> 2, c = (tid & 3) * 4;
            float4 av = *(const float4*)(A + (size_t)(m0 + r) * K + k0 + c);
            As[c + 0][r] = av.x; As[c + 1][r] = av.y; As[c + 2][r] = av.z; As[c + 3][r] = av.w;
        }
        {
            int r = tid >> 4, c = (tid & 15) * 4;
            float4 bv = *(const float4*)(B + (size_t)(k0 + r) * N + n0 + c);
            *(float4*)&Bs[r][c] = bv;
        }
        __syncthreads();
#pragma unroll
        for (int kk = 0; kk < 16; kk++) {
            float a[4], b[4];
#pragma unroll
            for (int i = 0; i < 4; i++) a[i] = As[kk][ty * 4 + i];
            float4 bv = *(float4*)&Bs[kk][tx * 4];
            b[0] = bv.x; b[1] = bv.y; b[2] = bv.z; b[3] = bv.w;
#pragma unroll
            for (int i = 0; i < 4; i++)
#pragma unroll
                for (int j = 0; j < 4; j++) acc[i][j] = fmaf(a[i], b[j], acc[i][j]);
        }
        __syncthreads();
    }
#pragma unroll
    for (int i = 0; i < 4; i++) {
        int m = m0 + ty * 4 + i;
#pragma unroll
        for (int j = 0; j < 4; j++) {
            int n = n0 + tx * 4 + j;
            float v = acc[i][j];
            if (bias) v += bias[n];
            if (act == 1) v = fmaxf(v, 0.f);
            else if (act == 2) v = (v > 0.f) ? v : expm1f(v);
            C[(size_t)m * N + n] = v;
        }
    }
}

// ---------------- GAT attention coefficients ----------------
__global__ void gat_alpha_coef(const float* __restrict__ h, const float* __restrict__ att_src,
                               const float* __restrict__ att_dst, float* as_, float* ad_, int H) {
    int i = blockIdx.x * blockDim.x + threadIdx.x;
    if (i >= NN * H) return;
    int n = i / H, hh = i % H;
    const float* hp = h + (size_t)n * H * HID + hh * HID;
    const float* s = att_src + hh * HID;
    const float* d = att_dst + hh * HID;
    float ss = 0.f, dd = 0.f;
#pragma unroll 8
    for (int c = 0; c < HID; c++) { ss = fmaf(hp[c], s[c], ss); dd = fmaf(hp[c], d[c], dd); }
    as_[i] = ss; ad_[i] = dd;
}

__global__ void gat_edge_max(const int* __restrict__ ei, const float* __restrict__ as_,
                             const float* __restrict__ ad_, float* m, int H) {
    int e = blockIdx.x * blockDim.x + threadIdx.x;
    if (e >= ETOT) return;
    int s = (e < EE) ? ei[e] : (e - EE);
    int d = (e < EE) ? ei[EE + e] : (e - EE);
    for (int h = 0; h < H; h++) {
        float x = as_[s * H + h] + ad_[d * H + h];
        x = (x >= 0.f) ? x : 0.2f * x;
        atomicMaxF(&m[d * H + h], x);
    }
}

__global__ void gat_edge_exp(const int* __restrict__ ei, const float* __restrict__ as_,
                             const float* __restrict__ ad_, const float* __restrict__ m,
                             float* denom, float* eexp, int H) {
    int e = blockIdx.x * blockDim.x + threadIdx.x;
    if (e >= ETOT) return;
    int s = (e < EE) ? ei[e] : (e - EE);
    int d = (e < EE) ? ei[EE + e] : (e - EE);
    for (int h = 0; h < H; h++) {
        float x = as_[s * H + h] + ad_[d * H + h];
        x = (x >= 0.f) ? x : 0.2f * x;
        float ex = expf(x - m[d * H + h]);
        eexp[e * H + h] = ex;
        atomicAdd(&denom[d * H + h], ex);
    }
}

// one warp per (edge, head); HID=64 -> 2 floats per lane
__global__ void gat_edge_aggr(const int* __restrict__ ei, const float* __restrict__ h,
                              const float* __restrict__ eexp, const float* __restrict__ denom,
                              float* out, int H) {
    int w = (blockIdx.x * blockDim.x + threadIdx.x) >> 5;
    int lane = threadIdx.x & 31;
    if (w >= ETOT * H) return;
    int e = w / H, hh = w - e * H;
    int s = (e < EE) ? ei[e] : (e - EE);
    int d = (e < EE) ? ei[EE + e] : (e - EE);
    float alpha = eexp[e * H + hh] / (denom[d * H + hh] + 1e-16f);
    const float* hs = h + (size_t)s * H * HID + hh * HID;
    float* od = out + (size_t)d * H * HID + hh * HID;
    atomicAdd(&od[lane], alpha * hs[lane]);
    atomicAdd(&od[lane + 32], alpha * hs[lane + 32]);
}

__global__ void bias_act_kernel(const float* __restrict__ in, const float* __restrict__ bias,
                                float* out, int M, int N, int act) {
    int i = blockIdx.x * blockDim.x + threadIdx.x;
    if (i >= M * N) return;
    int n = i % N;
    float v = in[i] + bias[n];
    if (act == 1) v = fmaxf(v, 0.f);
    else if (act == 2) v = (v > 0.f) ? v : expm1f(v);
    out[i] = v;
}

// ---------------- GCN ----------------
__global__ void deg_kernel(const int* __restrict__ ei, float* deg) {
    int e = blockIdx.x * blockDim.x + threadIdx.x;
    if (e >= ETOT) return;
    int d = (e < EE) ? ei[EE + e] : (e - EE);
    atomicAdd(&deg[d], 1.0f);
}

__global__ void dinv_kernel(const float* deg, float* dinv) {
    int i = blockIdx.x * blockDim.x + threadIdx.x;
    if (i < NN) dinv[i] = rsqrtf(fmaxf(deg[i], 1.0f));
}

__global__ void gcn_aggr(const int* __restrict__ ei, const float* __restrict__ hg,
                         const float* __restrict__ dinv, float* out) {
    int w = (blockIdx.x * blockDim.x + threadIdx.x) >> 5;
    int lane = threadIdx.x & 31;
    if (w >= ETOT) return;
    int s = (w < EE) ? ei[w] : (w - EE);
    int d = (w < EE) ? ei[EE + w] : (w - EE);
    float nrm = dinv[s] * dinv[d];
    const float* hs = hg + (size_t)s * 64;
    float* od = out + (size_t)d * 64;
    atomicAdd(&od[lane], nrm * hs[lane]);
    atomicAdd(&od[lane + 32], nrm * hs[lane + 32]);
}

// ---------------- attention: S[h][q][k] = scale * Q[q,h,:] . K[k,h,:] ----------------
// BM=BN=128, K=32 full depth, 256 threads, 8x8 per thread.
__global__ __launch_bounds__(256) void qk_kernel(const float* __restrict__ Q,
                                                 const float* __restrict__ Kmat,
                                                 float* __restrict__ S) {
    __shared__ float Qs[128][33];    // [r][c]
    __shared__ float Kt[32][132];    // [c][r]  (row stride 132 -> 16B aligned vec loads)
    int h = blockIdx.z;
    int q0 = blockIdx.y * 128, k0 = blockIdx.x * 128;
    int tid = threadIdx.x, tx = tid & 15, ty = tid >> 4;
#pragma unroll
    for (int i = 0; i < 4; i++) {
        int idx = tid + i * 256;
        int r = idx >> 3, c = (idx & 7) * 4;
        float4 v = *(const float4*)(Q + (size_t)(q0 + r) * 64 + h * 32 + c);
        Qs[r][c] = v.x; Qs[r][c + 1] = v.y; Qs[r][c + 2] = v.z; Qs[r][c + 3] = v.w;
        float4 kv = *(const float4*)(Kmat + (size_t)(k0 + r) * 64 + h * 32 + c);
        Kt[c][r] = kv.x; Kt[c + 1][r] = kv.y; Kt[c + 2][r] = kv.z; Kt[c + 3][r] = kv.w;
    }
    __syncthreads();
    float acc[8][8] = {};
#pragma unroll
    for (int c = 0; c < 32; c++) {
        float a[8], b[8];
#pragma unroll
        for (int i = 0; i < 8; i++) a[i] = Qs[ty * 8 + i][c];
        float4 b0 = *(float4*)&Kt[c][tx * 8];
        float4 b1 = *(float4*)&Kt[c][tx * 8 + 4];
        b[0] = b0.x; b[1] = b0.y; b[2] = b0.z; b[3] = b0.w;
        b[4] = b1.x; b[5] = b1.y; b[6] = b1.z; b[7] = b1.w;
#pragma unroll
        for (int i = 0; i < 8; i++)
#pragma unroll
            for (int j = 0; j < 8; j++) acc[i][j] = fmaf(a[i], b[j], acc[i][j]);
    }
    const float scale = 0.17677669529663687f;  // 1/sqrt(32)
    float* Sp = S + (size_t)h * NN * NN;
#pragma unroll
    for (int i = 0; i < 8; i++) {
        size_t base = (size_t)(q0 + ty * 8 + i) * NN + k0 + tx * 8;
        float4 o0, o1;
        o0.x = acc[i][0] * scale; o0.y = acc[i][1] * scale; o0.z = acc[i][2] * scale; o0.w = acc[i][3] * scale;
        o1.x = acc[i][4] * scale; o1.y = acc[i][5] * scale; o1.z = acc[i][6] * scale; o1.w = acc[i][7] * scale;
        *(float4*)(Sp + base) = o0;
        *(float4*)(Sp + base + 4) = o1;
    }
}

// per-(q,head) row softmax in place; row fits in smem
__global__ __launch_bounds__(256) void softmax_kernel(float* __restrict__ S) {
    __shared__ float row[NN];
    __shared__ float red[256];
    int q = blockIdx.x, h = blockIdx.y;
    float* Sp = S + ((size_t)h * NN + q) * NN;
    int tid = threadIdx.x;
    float mx = -INFINITY;
#pragma unroll
    for (int j = 0; j < 8; j++) {
        int i4 = (tid + j * 256) * 4;
        float4 v = *(const float4*)(Sp + i4);
        *(float4*)&row[i4] = v;
        mx = fmaxf(mx, fmaxf(fmaxf(v.x, v.y), fmaxf(v.z, v.w)));
    }
    red[tid] = mx; __syncthreads();
    for (int s = 128; s > 0; s >>= 1) { if (tid < s) red[tid] = fmaxf(red[tid], red[tid + s]); __syncthreads(); }
    mx = red[0];
    __syncthreads();
    float sum = 0.f;
#pragma unroll
    for (int j = 0; j < 8; j++) {
        int i4 = (tid + j * 256) * 4;
        float4 v = *(float4*)&row[i4];
        v.x = __expf(v.x - mx); v.y = __expf(v.y - mx); v.z = __expf(v.z - mx); v.w = __expf(v.w - mx);
        *(float4*)&row[i4] = v;
        sum += v.x + v.y + v.z + v.w;
    }
    red[tid] = sum; __syncthreads();
    for (int s = 128; s > 0; s >>= 1) { if (tid < s) red[tid] += red[tid + s]; __syncthreads(); }
    float inv = 1.0f / red[0];
#pragma unroll
    for (int j = 0; j < 8; j++) {
        int i4 = (tid + j * 256) * 4;
        float4 v = *(float4*)&row[i4];
        v.x *= inv; v.y *= inv; v.z *= inv; v.w *= inv;
        *(float4*)(Sp + i4) = v;
    }
}

// out[q, h*32+d] = sum_k P[h][q][k] * V[k][h*32+d]; also writes averaged weights.
// grid.x = q tiles (NN/64), grid.y = ksplit(4). BM=64 rows, 64 cols (both heads), BK=32.
__global__ __launch_bounds__(256) void av_avg_kernel(const float* __restrict__ S,
                                                     const float* __restrict__ V,
                                                     float* __restrict__ out,
                                                     float* __restrict__ avg) {
    __shared__ float P0s[32][65];   // [k][r]
    __shared__ float P1s[32][65];
    __shared__ float Vs[32][64];    // [k][c]
    int q0 = blockIdx.x * 64;
    int kbase = blockIdx.y * (NN / 4);
    int tid = threadIdx.x, tx = tid & 15, ty = tid >> 4;
    float acc[4][4] = {};
    const float* Ph = (tx < 8) ? &P0s[0][0] : &P1s[0][0];
    for (int kb = 0; kb < NN / 4; kb += 32) {
#pragma unroll
        for (int i = 0; i < 2; i++) {
            int idx = tid + i * 256;          // 512 float4 of P tile
            int r = idx >> 3;
            int kc = (idx & 7) * 4;
            size_t goff = (size_t)(q0 + r) * NN + kbase + kb + kc;
            float4 p0 = *(const float4*)(S + goff);
            float4 p1 = *(const float4*)(S + (size_t)NN * NN + goff);
            float4 a;
            a.x = 0.5f * (p0.x + p1.x); a.y = 0.5f * (p0.y + p1.y);
            a.z = 0.5f * (p0.z + p1.z); a.w = 0.5f * (p0.w + p1.w);
            *(float4*)(avg + goff) = a;
            P0s[kc + 0][r] = p0.x; P0s[kc + 1][r] = p0.y; P0s[kc + 2][r] = p0.z; P0s[kc + 3][r] = p0.w;
            P1s[kc + 0][r] = p1.x; P1s[kc + 1][r] = p1.y; P1s[kc + 2][r] = p1.z; P1s[kc + 3][r] = p1.w;
        }
#pragma unroll
        for (int i = 0; i < 2; i++) {
            int idx = tid + i * 256;          // 512 float4 of V tile
            int kr = idx >> 4, c = (idx & 15) * 4;
            *(float4*)&Vs[kr][c] = *(const float4*)(V + (size_t)(kbase + kb + kr) * 64 + c);
        }
        __syncthreads();
#pragma unroll
        for (int kk = 0; kk < 32; kk++) {
            float a[4], b[4];
            const float* Pp = Ph + kk * 65;
#pragma unroll
            for (int i = 0; i < 4; i++) a[i] = Pp[ty * 4 + i];
            float4 bv = *(float4*)&Vs[kk][tx * 4];
            b[0] = bv.x; b[1] = bv.y; b[2] = bv.z; b[3] = bv.w;
#pragma unroll
            for (int i = 0; i < 4; i++)
#pragma unroll
                for (int j = 0; j < 4; j++) acc[i][j] = fmaf(a[i], b[j], acc[i][j]);
        }
        __syncthreads();
    }
#pragma unroll
    for (int i = 0; i < 4; i++)
#pragma unroll
        for (int j = 0; j < 4; j++)
            atomicAdd(&out[(size_t)(q0 + ty * 4 + i) * 64 + tx * 4 + j], acc[i][j]);
}

// ---------------- misc tail ----------------
__global__ void concat_kernel(const float* __restrict__ a, const float* __restrict__ b,
                              float* __restrict__ o) {
    int i = blockIdx.x * blockDim.x + threadIdx.x;
    if (i >= NN * 128) return;
    int n = i >> 7, c = i & 127;
    o[i] = (c < 64) ? a[n * 64 + c] : b[n * 64 + c - 64];
}

__global__ void fc2_kernel(const float* __restrict__ t, const float* __restrict__ W,
                           const float* __restrict__ b, float* __restrict__ pred) {
    int w = (blockIdx.x * blockDim.x + threadIdx.x) >> 5;
    int lane = threadIdx.x & 31;
    if (w >= NN) return;
    float s = t[(size_t)w * 64 + lane] * W[lane] + t[(size_t)w * 64 + lane + 32] * W[lane + 32];
#pragma unroll
    for (int off = 16; off > 0; off >>= 1) s += __shfl_down_sync(0xffffffffu, s, off);
    if (lane == 0) pred[w] = s + b[0];
}

// ---------------- launch ----------------
extern "C" void kernel_launch(void* const* d_in, const int* in_sizes, int n_in,
                              void* d_out, int out_size) {
    const float* x       = (const float*)d_in[0];
    const int*   eit     = (const int*)d_in[1];
    const int*   eie     = (const int*)d_in[2];
    const float* gat1_W  = (const float*)d_in[3];
    const float* gat1_as = (const float*)d_in[4];
    const float* gat1_ad = (const float*)d_in[5];
    const float* gat1_b  = (const float*)d_in[6];
    const float* gat2_W  = (const float*)d_in[7];
    const float* gat2_as = (const float*)d_in[8];
    const float* gat2_ad = (const float*)d_in[9];
    const float* gat2_b  = (const float*)d_in[10];
    const float* gcn1_W  = (const float*)d_in[11];
    const float* gcn1_b  = (const float*)d_in[12];
    const float* gcn2_W  = (const float*)d_in[13];
    const float* gcn2_b  = (const float*)d_in[14];
    const float* Wq = (const float*)d_in[15]; const float* bq = (const float*)d_in[16];
    const float* Wk = (const float*)d_in[17]; const float* bk = (const float*)d_in[18];
    const float* Wv = (const float*)d_in[19]; const float* bv = (const float*)d_in[20];
    const float* Wo = (const float*)d_in[21]; const float* bo = (const float*)d_in[22];
    const float* fc1_W = (const float*)d_in[23]; const float* fc1_b = (const float*)d_in[24];
    const float* fc2_W = (const float*)d_in[25]; const float* fc2_b = (const float*)d_in[26];

    float* out_pred = (float*)d_out;
    float* out_attn = (float*)d_out + NN;

    float *pS, *ph1, *pagg1, *pht1, *ph2, *pagg2, *phtkg;
    float *pas1, *pad1, *pm1, *pd1, *pe1, *pas2, *pad2, *pm2, *pd2, *pe2;
    float *pdeg, *pdinv, *pg1, *page1, *phe1, *pg2, *page2, *phekg;
    float *pq, *pk, *pv, *pao, *phat, *pfus, *pt1;
    cudaGetSymbolAddress((void**)&pS, g_S);
    cudaGetSymbolAddress((void**)&ph1, g_h1);     cudaGetSymbolAddress((void**)&pagg1, g_agg1);
    cudaGetSymbolAddress((void**)&pht1, g_ht1);   cudaGetSymbolAddress((void**)&ph2, g_h2);
    cudaGetSymbolAddress((void**)&pagg2, g_agg2); cudaGetSymbolAddress((void**)&phtkg, g_htkg);
    cudaGetSymbolAddress((void**)&pas1, g_as1);   cudaGetSymbolAddress((void**)&pad1, g_ad1);
    cudaGetSymbolAddress((void**)&pm1, g_m1);     cudaGetSymbolAddress((void**)&pd1, g_d1);
    cudaGetSymbolAddress((void**)&pe1, g_eexp1);
    cudaGetSymbolAddress((void**)&pas2, g_as2);   cudaGetSymbolAddress((void**)&pad2, g_ad2);
    cudaGetSymbolAddress((void**)&pm2, g_m2);     cudaGetSymbolAddress((void**)&pd2, g_d2);
    cudaGetSymbolAddress((void**)&pe2, g_eexp2);
    cudaGetSymbolAddress((void**)&pdeg, g_deg);   cudaGetSymbolAddress((void**)&pdinv, g_dinv);
    cudaGetSymbolAddress((void**)&pg1, g_g1);     cudaGetSymbolAddress((void**)&page1, g_agge1);
    cudaGetSymbolAddress((void**)&phe1, g_he1);   cudaGetSymbolAddress((void**)&pg2, g_g2);
    cudaGetSymbolAddress((void**)&page2, g_agge2);cudaGetSymbolAddress((void**)&phekg, g_hekg);
    cudaGetSymbolAddress((void**)&pq, g_q);       cudaGetSymbolAddress((void**)&pk, g_k);
    cudaGetSymbolAddress((void**)&pv, g_v);       cudaGetSymbolAddress((void**)&pao, g_attnout);
    cudaGetSymbolAddress((void**)&phat, g_hattn); cudaGetSymbolAddress((void**)&pfus, g_fused);
    cudaGetSymbolAddress((void**)&pt1, g_t1);

    const int T = 256;
    const int EB = (ETOT + T - 1) / T;

    // ===== GAT layer 1 (heads=2, concat) =====
    gemm64<<<dim3(2, 128), 256>>>(x, gat1_W, nullptr, ph1, NN, 128, DIN, 0);
    gat_alpha_coef<<<(NN * 2 + T - 1) / T, T>>>(ph1, gat1_as, gat1_ad, pas1, pad1, 2);
    fill_kernel<<<(NN * 2 + T - 1) / T, T>>>(pm1, -INFINITY, NN * 2);
    cudaMemsetAsync(pd1, 0, NN * 2 * sizeof(float));
    cudaMemsetAsync(pagg1, 0, (size_t)NN * 128 * sizeof(float));
    gat_edge_max<<<EB, T>>>(eit, pas1, pad1, pm1, 2);
    gat_edge_exp<<<EB, T>>>(eit, pas1, pad1, pm1, pd1, pe1, 2);
    gat_edge_aggr<<<(ETOT * 2 * 32 + T - 1) / T, T>>>(eit, ph1, pe1, pd1, pagg1, 2);
    bias_act_kernel<<<(NN * 128 + T - 1) / T, T>>>(pagg1, gat1_b, pht1, NN, 128, 2);

    // ===== GAT layer 2 (heads=1, mean) =====
    gemm64<<<dim3(1, 128), 256>>>(pht1, gat2_W, nullptr, ph2, NN, 64, 128, 0);
    gat_alpha_coef<<<(NN + T - 1) / T, T>>>(ph2, gat2_as, gat2_ad, pas2, pad2, 1);
    fill_kernel<<<(NN + T - 1) / T, T>>>(pm2, -INFINITY, NN);
    cudaMemsetAsync(pd2, 0, NN * sizeof(float));
    cudaMemsetAsync(pagg2, 0, (size_t)NN * 64 * sizeof(float));
    gat_edge_max<<<EB, T>>>(eit, pas2, pad2, pm2, 1);
    gat_edge_exp<<<EB, T>>>(eit, pas2, pad2, pm2, pd2, pe2, 1);
    gat_edge_aggr<<<(ETOT * 32 + T - 1) / T, T>>>(eit, ph2, pe2, pd2, pagg2, 1);
    bias_act_kernel<<<(NN * 64 + T - 1) / T, T>>>(pagg2, gat2_b, phtkg, NN, 64, 2);

    // ===== GCN branch =====
    cudaMemsetAsync(pdeg, 0, NN * sizeof(float));
    deg_kernel<<<EB, T>>>(eie, pdeg);
    dinv_kernel<<<(NN + T - 1) / T, T>>>(pdeg, pdinv);
    gemm64<<<dim3(1, 128), 256>>>(x, gcn1_W, nullptr, pg1, NN, 64, DIN, 0);
    cudaMemsetAsync(page1, 0, (size_t)NN * 64 * sizeof(float));
    gcn_aggr<<<(ETOT * 32 + T - 1) / T, T>>>(eie, pg1, pdinv, page1);
    bias_act_kernel<<<(NN * 64 + T - 1) / T, T>>>(page1, gcn1_b, phe1, NN, 64, 1);
    gemm64<<<dim3(1, 128), 256>>>(phe1, gcn2_W, nullptr, pg2, NN, 64, 64, 0);
    cudaMemsetAsync(page2, 0, (size_t)NN * 64 * sizeof(float));
    gcn_aggr<<<(ETOT * 32 + T - 1) / T, T>>>(eie, pg2, pdinv, page2);
    bias_act_kernel<<<(NN * 64 + T - 1) / T, T>>>(page2, gcn2_b, phekg, NN, 64, 1);

    // ===== cross attention =====
    gemm64<<<dim3(1, 128), 256>>>(phtkg, Wq, bq, pq, NN, 64, 64, 0);
    gemm64<<<dim3(1, 128), 256>>>(phekg, Wk, bk, pk, NN, 64, 64, 0);
    gemm64<<<dim3(1, 128), 256>>>(phekg, Wv, bv, pv, NN, 64, 64, 0);
    qk_kernel<<<dim3(64, 64, 2), 256>>>(pq, pk, pS);
    softmax_kernel<<<dim3(NN, 2), 256>>>(pS);
    cudaMemsetAsync(pao, 0, (size_t)NN * 64 * sizeof(float));
    av_avg_kernel<<<dim3(128, 4), 256>>>(pS, pv, pao, out_attn);
    gemm64<<<dim3(1, 128), 256>>>(pao, Wo, bo, phat, NN, 64, 64, 0);

    // ===== head =====
    concat_kernel<<<(NN * 128 + T - 1) / T, T>>>(phtkg, phat, pfus);
    gemm64<<<dim3(1, 128), 256>>>(pfus, fc1_W, fc1_b, pt1, NN, 64, 128, 1);
    fc2_kernel<<<(NN * 32 + T - 1) / T, T>>>(pt1, fc2_W, fc2_b, out_pred);
}

// round 2
// speedup vs baseline: 1.1126x; 1.1126x over previous
#include <cuda_runtime.h>
#include <math.h>

#define NN 8192
#define EE 262144
#define ETOT (EE + NN)
#define DIN 256
#define HID 64

// ---------------- scratch (device globals; no allocation allowed) ----------------
static __device__ float g_S[(size_t)2 * NN * NN];          // per-head unnormalized exp scores
static __device__ float g_h1[NN * 128];
static __device__ float g_agg1[NN * 128];
static __device__ float g_ht1[NN * 128];
static __device__ float g_h2[NN * 64];
static __device__ float g_agg2[NN * 64];
static __device__ float g_htkg[NN * 64];
static __device__ float g_as1[NN * 2], g_ad1[NN * 2], g_m1[NN * 2], g_d1[NN * 2];
static __device__ float g_eexp1[ETOT * 2];
static __device__ float g_as2[NN], g_ad2[NN], g_m2[NN], g_d2[NN];
static __device__ float g_eexp2[ETOT];
static __device__ float g_deg[NN], g_dinv[NN];
static __device__ float g_g1[NN * 64], g_agge1[NN * 64], g_he1[NN * 64];
static __device__ float g_g2[NN * 64], g_agge2[NN * 64], g_hekg[NN * 64];
static __device__ float g_q[NN * 64], g_k[NN * 64], g_v[NN * 64];
static __device__ float g_attnout[NN * 64];
static __device__ float g_hattn[NN * 64];
static __device__ float g_fused[NN * 128];
static __device__ float g_t1[NN * 64];
static __device__ float g_qn[NN * 2];      // per (q,head) L2 norm of q
static __device__ float g_knm[2];          // per head max_k ||k||
static __device__ float g_dsum[NN * 2];    // per (q,head) softmax denominator

// ---------------- helpers ----------------
__device__ __forceinline__ void atomicMaxF(float* addr, float v) {
    if (v >= 0.f) atomicMax((int*)addr, __float_as_int(v));
    else          atomicMin((unsigned int*)addr, __float_as_uint(v));
}

#define FMA2(d, a, b) asm("fma.rn.f32x2 %0, %1, %2, %3;" : "=l"(d) : "l"(a), "l"(b), "l"(d))
#define PACK2(d, f)   asm("mov.b64 %0, {%1, %1};" : "=l"(d) : "r"(__float_as_uint(f)))
#define UNPACK2(lo, hi, p) asm("mov.b64 {%0, %1}, %2;" : "=r"(lo), "=r"(hi) : "l"(p))

__global__ void fill_kernel(float* p, float v, int n) {
    int i = blockIdx.x * blockDim.x + threadIdx.x;
    if (i < n) p[i] = v;
}

// ---------------- generic tiled GEMM: C = act(A[M,K] @ B[K,N] + bias) ----------------
__global__ __launch_bounds__(256) void gemm64(const float* __restrict__ A,
                                              const float* __restrict__ B,
                                              const float* __restrict__ bias,
                                              float* __restrict__ C,
                                              int M, int N, int K, int act) {
    __shared__ float As[16][65];
    __shared__ float Bs[16][64];
    int tid = threadIdx.x;
    int tx = tid & 15, ty = tid >> 4;
    int m0 = blockIdx.y * 64, n0 = blockIdx.x * 64;
    float acc[4][4] = {};
    for (int k0 = 0; k0 < K; k0 += 16) {
        {
            int r = tid >> 2, c = (tid & 3) * 4;
            float4 av = *(const float4*)(A + (size_t)(m0 + r) * K + k0 + c);
            As[c + 0][r] = av.x; As[c + 1][r] = av.y; As[c + 2][r] = av.z; As[c + 3][r] = av.w;
        }
        {
            int r = tid >> 4, c = (tid & 15) * 4;
            float4 bv = *(const float4*)(B + (size_t)(k0 + r) * N + n0 + c);
            *(float4*)&Bs[r][c] = bv;
        }
        __syncthreads();
#pragma unroll
        for (int kk = 0; kk < 16; kk++) {
            float a[4], b[4];
#pragma unroll
            for (int i = 0; i < 4; i++) a[i] = As[kk][ty * 4 + i];
            float4 bv = *(float4*)&Bs[kk][tx * 4];
            b[0] = bv.x; b[1] = bv.y; b[2] = bv.z; b[3] = bv.w;
#pragma unroll
            for (int i = 0; i < 4; i++)
#pragma unroll
                for (int j = 0; j < 4; j++) acc[i][j] = fmaf(a[i], b[j], acc[i][j]);
        }
        __syncthreads();
    }
#pragma unroll
    for (int i = 0; i < 4; i++) {
        int m = m0 + ty * 4 + i;
#pragma unroll
        for (int j = 0; j < 4; j++) {
            int n = n0 + tx * 4 + j;
            float v = acc[i][j];
            if (bias) v += bias[n];
            if (act == 1) v = fmaxf(v, 0.f);
            else if (act == 2) v = (v > 0.f) ? v : expm1f(v);
            C[(size_t)m * N + n] = v;
        }
    }
}

// ---------------- GAT attention coefficients ----------------
__global__ void gat_alpha_coef(const float* __restrict__ h, const float* __restrict__ att_src,
                               const float* __restrict__ att_dst, float* as_, float* ad_, int H) {
    int i = blockIdx.x * blockDim.x + threadIdx.x;
    if (i >= NN * H) return;
    int n = i / H, hh = i % H;
    const float* hp = h + (size_t)n * H * HID + hh * HID;
    const float* s = att_src + hh * HID;
    const float* d = att_dst + hh * HID;
    float ss = 0.f, dd = 0.f;
#pragma unroll 8
    for (int c = 0; c < HID; c++) { ss = fmaf(hp[c], s[c], ss); dd = fmaf(hp[c], d[c], dd); }
    as_[i] = ss; ad_[i] = dd;
}

__global__ void gat_edge_max(const int* __restrict__ ei, const float* __restrict__ as_,
                             const float* __restrict__ ad_, float* m, int H) {
    int e = blockIdx.x * blockDim.x + threadIdx.x;
    if (e >= ETOT) return;
    int s = (e < EE) ? ei[e] : (e - EE);
    int d = (e < EE) ? ei[EE + e] : (e - EE);
    for (int h = 0; h < H; h++) {
        float x = as_[s * H + h] + ad_[d * H + h];
        x = (x >= 0.f) ? x : 0.2f * x;
        atomicMaxF(&m[d * H + h], x);
    }
}

__global__ void gat_edge_exp(const int* __restrict__ ei, const float* __restrict__ as_,
                             const float* __restrict__ ad_, const float* __restrict__ m,
                             float* denom, float* eexp, int H) {
    int e = blockIdx.x * blockDim.x + threadIdx.x;
    if (e >= ETOT) return;
    int s = (e < EE) ? ei[e] : (e - EE);
    int d = (e < EE) ? ei[EE + e] : (e - EE);
    for (int h = 0; h < H; h++) {
        float x = as_[s * H + h] + ad_[d * H + h];
        x = (x >= 0.f) ? x : 0.2f * x;
        float ex = expf(x - m[d * H + h]);
        eexp[e * H + h] = ex;
        atomicAdd(&denom[d * H + h], ex);
    }
}

// one warp per (edge, head); HID=64 -> 2 floats per lane
__global__ void gat_edge_aggr(const int* __restrict__ ei, const float* __restrict__ h,
                              const float* __restrict__ eexp, const float* __restrict__ denom,
                              float* out, int H) {
    int w = (blockIdx.x * blockDim.x + threadIdx.x) >> 5;
    int lane = threadIdx.x & 31;
    if (w >= ETOT * H) return;
    int e = w / H, hh = w - e * H;
    int s = (e < EE) ? ei[e] : (e - EE);
    int d = (e < EE) ? ei[EE + e] : (e - EE);
    float alpha = eexp[e * H + hh] / (denom[d * H + hh] + 1e-16f);
    const float* hs = h + (size_t)s * H * HID + hh * HID;
    float* od = out + (size_t)d * H * HID + hh * HID;
    atomicAdd(&od[lane], alpha * hs[lane]);
    atomicAdd(&od[lane + 32], alpha * hs[lane + 32]);
}

__global__ void bias_act_kernel(const float* __restrict__ in, const float* __restrict__ bias,
                                float* out, int M, int N, int act) {
    int i = blockIdx.x * blockDim.x + threadIdx.x;
    if (i >= M * N) return;
    int n = i % N;
    float v = in[i] + bias[n];
    if (act == 1) v = fmaxf(v, 0.f);
    else if (act == 2) v = (v > 0.f) ? v : expm1f(v);
    out[i] = v;
}

// ---------------- GCN ----------------
__global__ void deg_kernel(const int* __restrict__ ei, float* deg) {
    int e = blockIdx.x * blockDim.x + threadIdx.x;
    if (e >= ETOT) return;
    int d = (e < EE) ? ei[EE + e] : (e - EE);
    atomicAdd(&deg[d], 1.0f);
}

__global__ void dinv_kernel(const float* deg, float* dinv) {
    int i = blockIdx.x * blockDim.x + threadIdx.x;
    if (i < NN) dinv[i] = rsqrtf(fmaxf(deg[i], 1.0f));
}

__global__ void gcn_aggr(const int* __restrict__ ei, const float* __restrict__ hg,
                         const float* __restrict__ dinv, float* out) {
    int w = (blockIdx.x * blockDim.x + threadIdx.x) >> 5;
    int lane = threadIdx.x & 31;
    if (w >= ETOT) return;
    int s = (w < EE) ? ei[w] : (w - EE);
    int d = (w < EE) ? ei[EE + w] : (w - EE);
    float nrm = dinv[s] * dinv[d];
    const float* hs = hg + (size_t)s * 64;
    float* od = out + (size_t)d * 64;
    atomicAdd(&od[lane], nrm * hs[lane]);
    atomicAdd(&od[lane + 32], nrm * hs[lane + 32]);
}

// ---------------- attention ----------------
// norms: qn[q*2+h] = ||q_h||, knm[h] = max_k ||k_h||  (Cauchy-Schwarz softmax shift)
__global__ void norms_kernel(const float* __restrict__ Q, const float* __restrict__ K,
                             float* qn, float* knm) {
    int i = blockIdx.x * blockDim.x + threadIdx.x;
    if (i >= NN * 2) return;
    int q = i >> 1, h = i & 1;
    const float* qp = Q + (size_t)q * 64 + h * 32;
    const float* kp = K + (size_t)q * 64 + h * 32;
    float sq = 0.f, sk = 0.f;
#pragma unroll
    for (int c = 0; c < 32; c++) { sq = fmaf(qp[c], qp[c], sq); sk = fmaf(kp[c], kp[c], sk); }
    qn[i] = sqrtf(sq);
    atomicMaxF(&knm[h], sqrtf(sk));
}

// E[h][q][k] = exp(scale*(q.k - ||q||*knm)); also accumulates row sums dsum[q*2+h].
// BM=BN=128, K=32, 256 threads, 8x8 per thread with packed f32x2 FMA.
__global__ __launch_bounds__(256) void qk_exp_kernel(const float* __restrict__ Q,
                                                     const float* __restrict__ Kmat,
                                                     const float* __restrict__ qn,
                                                     const float* __restrict__ knm,
                                                     float* __restrict__ S,
                                                     float* __restrict__ dsum) {
    __shared__ float Qs[128][33];
    __shared__ float Kt[32][132];
    int h = blockIdx.z;
    int q0 = blockIdx.y * 128, k0 = blockIdx.x * 128;
    int tid = threadIdx.x, tx = tid & 15, ty = tid >> 4;
#pragma unroll
    for (int i = 0; i < 4; i++) {
        int idx = tid + i * 256;
        int r = idx >> 3, c = (idx & 7) * 4;
        float4 v = *(const float4*)(Q + (size_t)(q0 + r) * 64 + h * 32 + c);
        Qs[r][c] = v.x; Qs[r][c + 1] = v.y; Qs[r][c + 2] = v.z; Qs[r][c + 3] = v.w;
        float4 kv = *(const float4*)(Kmat + (size_t)(k0 + r) * 64 + h * 32 + c);
        Kt[c][r] = kv.x; Kt[c + 1][r] = kv.y; Kt[c + 2][r] = kv.z; Kt[c + 3][r] = kv.w;
    }
    __syncthreads();
    unsigned long long acc2[8][4] = {};
#pragma unroll
    for (int c = 0; c < 32; c++) {
        unsigned long long av[8];
#pragma unroll
        for (int i = 0; i < 8; i++) PACK2(av[i], Qs[ty * 8 + i][c]);
        ulonglong2 bb0 = *(ulonglong2*)&Kt[c][tx * 8];
        ulonglong2 bb1 = *(ulonglong2*)&Kt[c][tx * 8 + 4];
        unsigned long long bv[4] = {bb0.x, bb0.y, bb1.x, bb1.y};
#pragma unroll
        for (int i = 0; i < 8; i++)
#pragma unroll
            for (int j = 0; j < 4; j++) FMA2(acc2[i][j], av[i], bv[j]);
    }
    const float scale = 0.17677669529663687f;  // 1/sqrt(32)
    float knmh = knm[h];
    float* Sp = S + (size_t)h * NN * NN;
#pragma unroll
    for (int i = 0; i < 8; i++) {
        int q = q0 + ty * 8 + i;
        float shift = qn[q * 2 + h] * knmh;
        float ev[8];
        float rs = 0.f;
#pragma unroll
        for (int j = 0; j < 4; j++) {
            unsigned int lo, hi;
            UNPACK2(lo, hi, acc2[i][j]);
            float e0 = __expf((__uint_as_float(lo) - shift) * scale);
            float e1 = __expf((__uint_as_float(hi) - shift) * scale);
            ev[2 * j] = e0; ev[2 * j + 1] = e1;
            rs += e0 + e1;
        }
        size_t base = (size_t)q * NN + k0 + tx * 8;
        float4 o0 = {ev[0], ev[1], ev[2], ev[3]};
        float4 o1 = {ev[4], ev[5], ev[6], ev[7]};
        *(float4*)(Sp + base) = o0;
        *(float4*)(Sp + base + 4) = o1;
#pragma unroll
        for (int off = 8; off > 0; off >>= 1) rs += __shfl_down_sync(0xffffffffu, rs, off, 16);
        if (tx == 0) atomicAdd(&dsum[q * 2 + h], rs);
    }
}

// out[q, h*32+d] = sum_k (E[h][q][k]/dsum) * V[k][h*32+d]; writes head-averaged weights.
__global__ __launch_bounds__(256) void av_avg_kernel(const float* __restrict__ S,
                                                     const float* __restrict__ V,
                                                     const float* __restrict__ dsum,
                                                     float* __restrict__ out,
                                                     float* __restrict__ avg) {
    __shared__ float P0s[32][65];
    __shared__ float P1s[32][65];
    __shared__ float Vs[32][64];
    __shared__ float invd0s[64], invd1s[64];
    int q0 = blockIdx.x * 64;
    int kbase = blockIdx.y * (NN / 4);
    int tid = threadIdx.x, tx = tid & 15, ty = tid >> 4;
    if (tid < 64) invd0s[tid] = 1.0f / dsum[(q0 + tid) * 2];
    else if (tid < 128) invd1s[tid - 64] = 1.0f / dsum[(q0 + tid - 64) * 2 + 1];
    __syncthreads();
    unsigned long long acc2[4][2] = {};
    const float* Ph = (tx < 8) ? &P0s[0][0] : &P1s[0][0];
    for (int kb = 0; kb < NN / 4; kb += 32) {
#pragma unroll
        for (int i = 0; i < 2; i++) {
            int idx = tid + i * 256;
            int r = idx >> 3;
            int kc = (idx & 7) * 4;
            size_t goff = (size_t)(q0 + r) * NN + kbase + kb + kc;
            float4 p0 = *(const float4*)(S + goff);
            float4 p1 = *(const float4*)(S + (size_t)NN * NN + goff);
            float i0 = invd0s[r], i1 = invd1s[r];
            p0.x *= i0; p0.y *= i0; p0.z *= i0; p0.w *= i0;
            p1.x *= i1; p1.y *= i1; p1.z *= i1; p1.w *= i1;
            float4 a;
            a.x = 0.5f * (p0.x + p1.x); a.y = 0.5f * (p0.y + p1.y);
            a.z = 0.5f * (p0.z + p1.z); a.w = 0.5f * (p0.w + p1.w);
            *(float4*)(avg + goff) = a;
            P0s[kc + 0][r] = p0.x; P0s[kc + 1][r] = p0.y; P0s[kc + 2][r] = p0.z; P0s[kc + 3][r] = p0.w;
            P1s[kc + 0][r] = p1.x; P1s[kc + 1][r] = p1.y; P1s[kc + 2][r] = p1.z; P1s[kc + 3][r] = p1.w;
        }
#pragma unroll
        for (int i = 0; i < 2; i++) {
            int idx = tid + i * 256;
            int kr = idx >> 4, c = (idx & 15) * 4;
            *(float4*)&Vs[kr][c] = *(const float4*)(V + (size_t)(kbase + kb + kr) * 64 + c);
        }
        __syncthreads();
#pragma unroll
        for (int kk = 0; kk < 32; kk++) {
            const float* Pp = Ph + kk * 65;
            ulonglong2 bb = *(ulonglong2*)&Vs[kk][tx * 4];
#pragma unroll
            for (int i = 0; i < 4; i++) {
                unsigned long long a2;
                PACK2(a2, Pp[ty * 4 + i]);
                FMA2(acc2[i][0], a2, bb.x);
                FMA2(acc2[i][1], a2, bb.y);
            }
        }
        __syncthreads();
    }
#pragma unroll
    for (int i = 0; i < 4; i++) {
#pragma unroll
        for (int j = 0; j < 2; j++) {
            unsigned int lo, hi;
            UNPACK2(lo, hi, acc2[i][j]);
            atomicAdd(&out[(size_t)(q0 + ty * 4 + i) * 64 + tx * 4 + 2 * j], __uint_as_float(lo));
            atomicAdd(&out[(size_t)(q0 + ty * 4 + i) * 64 + tx * 4 + 2 * j + 1], __uint_as_float(hi));
        }
    }
}

// ---------------- misc tail ----------------
__global__ void concat_kernel(const float* __restrict__ a, const float* __restrict__ b,
                              float* __restrict__ o) {
    int i = blockIdx.x * blockDim.x + threadIdx.x;
    if (i >= NN * 128) return;
    int n = i >> 7, c = i & 127;
    o[i] = (c < 64) ? a[n * 64 + c] : b[n * 64 + c - 64];
}

__global__ void fc2_kernel(const float* __restrict__ t, const float* __restrict__ W,
                           const float* __restrict__ b, float* __restrict__ pred) {
    int w = (blockIdx.x * blockDim.x + threadIdx.x) >> 5;
    int lane = threadIdx.x & 31;
    if (w >= NN) return;
    float s = t[(size_t)w * 64 + lane] * W[lane] + t[(size_t)w * 64 + lane + 32] * W[lane + 32];
#pragma unroll
    for (int off = 16; off > 0; off >>= 1) s += __shfl_down_sync(0xffffffffu, s, off);
    if (lane == 0) pred[w] = s + b[0];
}

// ---------------- launch ----------------
extern "C" void kernel_launch(void* const* d_in, const int* in_sizes, int n_in,
                              void* d_out, int out_size) {
    const float* x       = (const float*)d_in[0];
    const int*   eit     = (const int*)d_in[1];
    const int*   eie     = (const int*)d_in[2];
    const float* gat1_W  = (const float*)d_in[3];
    const float* gat1_as = (const float*)d_in[4];
    const float* gat1_ad = (const float*)d_in[5];
    const float* gat1_b  = (const float*)d_in[6];
    const float* gat2_W  = (const float*)d_in[7];
    const float* gat2_as = (const float*)d_in[8];
    const float* gat2_ad = (const float*)d_in[9];
    const float* gat2_b  = (const float*)d_in[10];
    const float* gcn1_W  = (const float*)d_in[11];
    const float* gcn1_b  = (const float*)d_in[12];
    const float* gcn2_W  = (const float*)d_in[13];
    const float* gcn2_b  = (const float*)d_in[14];
    const float* Wq = (const float*)d_in[15]; const float* bq = (const float*)d_in[16];
    const float* Wk = (const float*)d_in[17]; const float* bk = (const float*)d_in[18];
    const float* Wv = (const float*)d_in[19]; const float* bv = (const float*)d_in[20];
    const float* Wo = (const float*)d_in[21]; const float* bo = (const float*)d_in[22];
    const float* fc1_W = (const float*)d_in[23]; const float* fc1_b = (const float*)d_in[24];
    const float* fc2_W = (const float*)d_in[25]; const float* fc2_b = (const float*)d_in[26];

    float* out_pred = (float*)d_out;
    float* out_attn = (float*)d_out + NN;

    float *pS, *ph1, *pagg1, *pht1, *ph2, *pagg2, *phtkg;
    float *pas1, *pad1, *pm1, *pd1, *pe1, *pas2, *pad2, *pm2, *pd2, *pe2;
    float *pdeg, *pdinv, *pg1, *page1, *phe1, *pg2, *page2, *phekg;
    float *pq, *pk, *pv, *pao, *phat, *pfus, *pt1, *pqn, *pknm, *pdsum;
    cudaGetSymbolAddress((void**)&pS, g_S);
    cudaGetSymbolAddress((void**)&ph1, g_h1);     cudaGetSymbolAddress((void**)&pagg1, g_agg1);
    cudaGetSymbolAddress((void**)&pht1, g_ht1);   cudaGetSymbolAddress((void**)&ph2, g_h2);
    cudaGetSymbolAddress((void**)&pagg2, g_agg2); cudaGetSymbolAddress((void**)&phtkg, g_htkg);
    cudaGetSymbolAddress((void**)&pas1, g_as1);   cudaGetSymbolAddress((void**)&pad1, g_ad1);
    cudaGetSymbolAddress((void**)&pm1, g_m1);     cudaGetSymbolAddress((void**)&pd1, g_d1);
    cudaGetSymbolAddress((void**)&pe1, g_eexp1);
    cudaGetSymbolAddress((void**)&pas2, g_as2);   cudaGetSymbolAddress((void**)&pad2, g_ad2);
    cudaGetSymbolAddress((void**)&pm2, g_m2);     cudaGetSymbolAddress((void**)&pd2, g_d2);
    cudaGetSymbolAddress((void**)&pe2, g_eexp2);
    cudaGetSymbolAddress((void**)&pdeg, g_deg);   cudaGetSymbolAddress((void**)&pdinv, g_dinv);
    cudaGetSymbolAddress((void**)&pg1, g_g1);     cudaGetSymbolAddress((void**)&page1, g_agge1);
    cudaGetSymbolAddress((void**)&phe1, g_he1);   cudaGetSymbolAddress((void**)&pg2, g_g2);
    cudaGetSymbolAddress((void**)&page2, g_agge2);cudaGetSymbolAddress((void**)&phekg, g_hekg);
    cudaGetSymbolAddress((void**)&pq, g_q);       cudaGetSymbolAddress((void**)&pk, g_k);
    cudaGetSymbolAddress((void**)&pv, g_v);       cudaGetSymbolAddress((void**)&pao, g_attnout);
    cudaGetSymbolAddress((void**)&phat, g_hattn); cudaGetSymbolAddress((void**)&pfus, g_fused);
    cudaGetSymbolAddress((void**)&pt1, g_t1);
    cudaGetSymbolAddress((void**)&pqn, g_qn);     cudaGetSymbolAddress((void**)&pknm, g_knm);
    cudaGetSymbolAddress((void**)&pdsum, g_dsum);

    const int T = 256;
    const int EB = (ETOT + T - 1) / T;

    // ===== GAT layer 1 (heads=2, concat) =====
    gemm64<<<dim3(2, 128), 256>>>(x, gat1_W, nullptr, ph1, NN, 128, DIN, 0);
    gat_alpha_coef<<<(NN * 2 + T - 1) / T, T>>>(ph1, gat1_as, gat1_ad, pas1, pad1, 2);
    fill_kernel<<<(NN * 2 + T - 1) / T, T>>>(pm1, -INFINITY, NN * 2);
    cudaMemsetAsync(pd1, 0, NN * 2 * sizeof(float));
    cudaMemsetAsync(pagg1, 0, (size_t)NN * 128 * sizeof(float));
    gat_edge_max<<<EB, T>>>(eit, pas1, pad1, pm1, 2);
    gat_edge_exp<<<EB, T>>>(eit, pas1, pad1, pm1, pd1, pe1, 2);
    gat_edge_aggr<<<(ETOT * 2 * 32 + T - 1) / T, T>>>(eit, ph1, pe1, pd1, pagg1, 2);
    bias_act_kernel<<<(NN * 128 + T - 1) / T, T>>>(pagg1, gat1_b, pht1, NN, 128, 2);

    // ===== GAT layer 2 (heads=1, mean) =====
    gemm64<<<dim3(1, 128), 256>>>(pht1, gat2_W, nullptr, ph2, NN, 64, 128, 0);
    gat_alpha_coef<<<(NN + T - 1) / T, T>>>(ph2, gat2_as, gat2_ad, pas2, pad2, 1);
    fill_kernel<<<(NN + T - 1) / T, T>>>(pm2, -INFINITY, NN);
    cudaMemsetAsync(pd2, 0, NN * sizeof(float));
    cudaMemsetAsync(pagg2, 0, (size_t)NN * 64 * sizeof(float));
    gat_edge_max<<<EB, T>>>(eit, pas2, pad2, pm2, 1);
    gat_edge_exp<<<EB, T>>>(eit, pas2, pad2, pm2, pd2, pe2, 1);
    gat_edge_aggr<<<(ETOT * 32 + T - 1) / T, T>>>(eit, ph2, pe2, pd2, pagg2, 1);
    bias_act_kernel<<<(NN * 64 + T - 1) / T, T>>>(pagg2, gat2_b, phtkg, NN, 64, 2);

    // ===== GCN branch =====
    cudaMemsetAsync(pdeg, 0, NN * sizeof(float));
    deg_kernel<<<EB, T>>>(eie, pdeg);
    dinv_kernel<<<(NN + T - 1) / T, T>>>(pdeg, pdinv);
    gemm64<<<dim3(1, 128), 256>>>(x, gcn1_W, nullptr, pg1, NN, 64, DIN, 0);
    cudaMemsetAsync(page1, 0, (size_t)NN * 64 * sizeof(float));
    gcn_aggr<<<(ETOT * 32 + T - 1) / T, T>>>(eie, pg1, pdinv, page1);
    bias_act_kernel<<<(NN * 64 + T - 1) / T, T>>>(page1, gcn1_b, phe1, NN, 64, 1);
    gemm64<<<dim3(1, 128), 256>>>(phe1, gcn2_W, nullptr, pg2, NN, 64, 64, 0);
    cudaMemsetAsync(page2, 0, (size_t)NN * 64 * sizeof(float));
    gcn_aggr<<<(ETOT * 32 + T - 1) / T, T>>>(eie, pg2, pdinv, page2);
    bias_act_kernel<<<(NN * 64 + T - 1) / T, T>>>(page2, gcn2_b, phekg, NN, 64, 1);

    // ===== cross attention (fused softmax via Cauchy-Schwarz shift) =====
    gemm64<<<dim3(1, 128), 256>>>(phtkg, Wq, bq, pq, NN, 64, 64, 0);
    gemm64<<<dim3(1, 128), 256>>>(phekg, Wk, bk, pk, NN, 64, 64, 0);
    gemm64<<<dim3(1, 128), 256>>>(phekg, Wv, bv, pv, NN, 64, 64, 0);
    cudaMemsetAsync(pknm, 0, 2 * sizeof(float));
    cudaMemsetAsync(pdsum, 0, NN * 2 * sizeof(float));
    norms_kernel<<<(NN * 2 + T - 1) / T, T>>>(pq, pk, pqn, pknm);
    qk_exp_kernel<<<dim3(64, 64, 2), 256>>>(pq, pk, pqn, pknm, pS, pdsum);
    cudaMemsetAsync(pao, 0, (size_t)NN * 64 * sizeof(float));
    av_avg_kernel<<<dim3(128, 4), 256>>>(pS, pv, pdsum, pao, out_attn);
    gemm64<<<dim3(1, 128), 256>>>(pao, Wo, bo, phat, NN, 64, 64, 0);

    // ===== head =====
    concat_kernel<<<(NN * 128 + T - 1) / T, T>>>(phtkg, phat, pfus);
    gemm64<<<dim3(1, 128), 256>>>(pfus, fc1_W, fc1_b, pt1, NN, 64, 128, 1);
    fc2_kernel<<<(NN * 32 + T - 1) / T, T>>>(pt1, fc2_W, fc2_b, out_pred);
}

// round 3
// speedup vs baseline: 1.1606x; 1.0431x over previous
#include <cuda_runtime.h>
#include <cuda_fp16.h>
#include <math.h>

#define NN 8192
#define EE 262144
#define ETOT (EE + NN)
#define DIN 256
#define HID 64

// ---------------- scratch (device globals; no allocation allowed) ----------------
static __device__ __half g_S[(size_t)2 * NN * NN];         // 268 MB: per-head unnormalized exp scores (fp16)
static __device__ float g_h1[NN * 128];
static __device__ float g_agg1[NN * 128];
static __device__ float g_ht1[NN * 128];
static __device__ float g_h2[NN * 64];
static __device__ float g_agg2[NN * 64];
static __device__ float g_htkg[NN * 64];
static __device__ float g_as1[NN * 2], g_ad1[NN * 2], g_m1[NN * 2], g_d1[NN * 2];
static __device__ float g_eexp1[ETOT * 2];
static __device__ float g_as2[NN], g_ad2[NN], g_m2[NN], g_d2[NN];
static __device__ float g_eexp2[ETOT];
static __device__ float g_deg[NN], g_dinv[NN];
static __device__ float g_g1[NN * 64], g_agge1[NN * 64], g_he1[NN * 64];
static __device__ float g_g2[NN * 64], g_agge2[NN * 64], g_hekg[NN * 64];
static __device__ float g_q[NN * 64], g_k[NN * 64], g_v[NN * 64];
static __device__ float g_attnout[NN * 64];
static __device__ float g_hattn[NN * 64];
static __device__ float g_fused[NN * 128];
static __device__ float g_t1[NN * 64];
static __device__ float g_qn[NN * 2];      // per (q,head) L2 norm of q
static __device__ float g_knm[2];          // per head max_k ||k||
static __device__ float g_dsum[NN * 2];    // per (q,head) softmax denominator

// ---------------- helpers ----------------
__device__ __forceinline__ void atomicMaxF(float* addr, float v) {
    if (v >= 0.f) atomicMax((int*)addr, __float_as_int(v));
    else          atomicMin((unsigned int*)addr, __float_as_uint(v));
}

#define FMA2(d, a, b) asm("fma.rn.f32x2 %0, %1, %2, %3;" : "=l"(d) : "l"(a), "l"(b), "l"(d))
#define PACK2(d, f)   asm("mov.b64 %0, {%1, %1};" : "=l"(d) : "r"(__float_as_uint(f)))
#define UNPACK2(lo, hi, p) asm("mov.b64 {%0, %1}, %2;" : "=r"(lo), "=r"(hi) : "l"(p))

__global__ void fill_kernel(float* p, float v, int n) {
    int i = blockIdx.x * blockDim.x + threadIdx.x;
    if (i < n) p[i] = v;
}

// ---------------- generic tiled GEMM: C = act(A[M,K] @ B[K,N] + bias) ----------------
__global__ __launch_bounds__(256) void gemm64(const float* __restrict__ A,
                                              const float* __restrict__ B,
                                              const float* __restrict__ bias,
                                              float* __restrict__ C,
                                              int M, int N, int K, int act) {
    __shared__ float As[16][65];
    __shared__ float Bs[16][64];
    int tid = threadIdx.x;
    int tx = tid & 15, ty = tid >> 4;
    int m0 = blockIdx.y * 64, n0 = blockIdx.x * 64;
    float acc[4][4] = {};
    for (int k0 = 0; k0 < K; k0 += 16) {
        {
            int r = tid >> 2, c = (tid & 3) * 4;
            float4 av = *(const float4*)(A + (size_t)(m0 + r) * K + k0 + c);
            As[c + 0][r] = av.x; As[c + 1][r] = av.y; As[c + 2][r] = av.z; As[c + 3][r] = av.w;
        }
        {
            int r = tid >> 4, c = (tid & 15) * 4;
            float4 bv = *(const float4*)(B + (size_t)(k0 + r) * N + n0 + c);
            *(float4*)&Bs[r][c] = bv;
        }
        __syncthreads();
#pragma unroll
        for (int kk = 0; kk < 16; kk++) {
            float a[4], b[4];
#pragma unroll
            for (int i = 0; i < 4; i++) a[i] = As[kk][ty * 4 + i];
            float4 bv = *(float4*)&Bs[kk][tx * 4];
            b[0] = bv.x; b[1] = bv.y; b[2] = bv.z; b[3] = bv.w;
#pragma unroll
            for (int i = 0; i < 4; i++)
#pragma unroll
                for (int j = 0; j < 4; j++) acc[i][j] = fmaf(a[i], b[j], acc[i][j]);
        }
        __syncthreads();
    }
#pragma unroll
    for (int i = 0; i < 4; i++) {
        int m = m0 + ty * 4 + i;
#pragma unroll
        for (int j = 0; j < 4; j++) {
            int n = n0 + tx * 4 + j;
            float v = acc[i][j];
            if (bias) v += bias[n];
            if (act == 1) v = fmaxf(v, 0.f);
            else if (act == 2) v = (v > 0.f) ? v : expm1f(v);
            C[(size_t)m * N + n] = v;
        }
    }
}

// ---------------- GAT attention coefficients ----------------
__global__ void gat_alpha_coef(const float* __restrict__ h, const float* __restrict__ att_src,
                               const float* __restrict__ att_dst, float* as_, float* ad_, int H) {
    int i = blockIdx.x * blockDim.x + threadIdx.x;
    if (i >= NN * H) return;
    int n = i / H, hh = i % H;
    const float* hp = h + (size_t)n * H * HID + hh * HID;
    const float* s = att_src + hh * HID;
    const float* d = att_dst + hh * HID;
    float ss = 0.f, dd = 0.f;
#pragma unroll 8
    for (int c = 0; c < HID; c++) { ss = fmaf(hp[c], s[c], ss); dd = fmaf(hp[c], d[c], dd); }
    as_[i] = ss; ad_[i] = dd;
}

__global__ void gat_edge_max(const int* __restrict__ ei, const float* __restrict__ as_,
                             const float* __restrict__ ad_, float* m, int H) {
    int e = blockIdx.x * blockDim.x + threadIdx.x;
    if (e >= ETOT) return;
    int s = (e < EE) ? ei[e] : (e - EE);
    int d = (e < EE) ? ei[EE + e] : (e - EE);
    for (int h = 0; h < H; h++) {
        float x = as_[s * H + h] + ad_[d * H + h];
        x = (x >= 0.f) ? x : 0.2f * x;
        atomicMaxF(&m[d * H + h], x);
    }
}

__global__ void gat_edge_exp(const int* __restrict__ ei, const float* __restrict__ as_,
                             const float* __restrict__ ad_, const float* __restrict__ m,
                             float* denom, float* eexp, int H) {
    int e = blockIdx.x * blockDim.x + threadIdx.x;
    if (e >= ETOT) return;
    int s = (e < EE) ? ei[e] : (e - EE);
    int d = (e < EE) ? ei[EE + e] : (e - EE);
    for (int h = 0; h < H; h++) {
        float x = as_[s * H + h] + ad_[d * H + h];
        x = (x >= 0.f) ? x : 0.2f * x;
        float ex = expf(x - m[d * H + h]);
        eexp[e * H + h] = ex;
        atomicAdd(&denom[d * H + h], ex);
    }
}

// one warp per (edge, head); HID=64 -> 2 floats per lane
__global__ void gat_edge_aggr(const int* __restrict__ ei, const float* __restrict__ h,
                              const float* __restrict__ eexp, const float* __restrict__ denom,
                              float* out, int H) {
    int w = (blockIdx.x * blockDim.x + threadIdx.x) >> 5;
    int lane = threadIdx.x & 31;
    if (w >= ETOT * H) return;
    int e = w / H, hh = w - e * H;
    int s = (e < EE) ? ei[e] : (e - EE);
    int d = (e < EE) ? ei[EE + e] : (e - EE);
    float alpha = eexp[e * H + hh] / (denom[d * H + hh] + 1e-16f);
    const float* hs = h + (size_t)s * H * HID + hh * HID;
    float* od = out + (size_t)d * H * HID + hh * HID;
    atomicAdd(&od[lane], alpha * hs[lane]);
    atomicAdd(&od[lane + 32], alpha * hs[lane + 32]);
}

__global__ void bias_act_kernel(const float* __restrict__ in, const float* __restrict__ bias,
                                float* out, int M, int N, int act) {
    int i = blockIdx.x * blockDim.x + threadIdx.x;
    if (i >= M * N) return;
    int n = i % N;
    float v = in[i] + bias[n];
    if (act == 1) v = fmaxf(v, 0.f);
    else if (act == 2) v = (v > 0.f) ? v : expm1f(v);
    out[i] = v;
}

// ---------------- GCN ----------------
__global__ void deg_kernel(const int* __restrict__ ei, float* deg) {
    int e = blockIdx.x * blockDim.x + threadIdx.x;
    if (e >= ETOT) return;
    int d = (e < EE) ? ei[EE + e] : (e - EE);
    atomicAdd(&deg[d], 1.0f);
}

__global__ void dinv_kernel(const float* deg, float* dinv) {
    int i = blockIdx.x * blockDim.x + threadIdx.x;
    if (i < NN) dinv[i] = rsqrtf(fmaxf(deg[i], 1.0f));
}

__global__ void gcn_aggr(const int* __restrict__ ei, const float* __restrict__ hg,
                         const float* __restrict__ dinv, float* out) {
    int w = (blockIdx.x * blockDim.x + threadIdx.x) >> 5;
    int lane = threadIdx.x & 31;
    if (w >= ETOT) return;
    int s = (w < EE) ? ei[w] : (w - EE);
    int d = (w < EE) ? ei[EE + w] : (w - EE);
    float nrm = dinv[s] * dinv[d];
    const float* hs = hg + (size_t)s * 64;
    float* od = out + (size_t)d * 64;
    atomicAdd(&od[lane], nrm * hs[lane]);
    atomicAdd(&od[lane + 32], nrm * hs[lane + 32]);
}

// ---------------- attention ----------------
// norms: qn[q*2+h] = ||q_h||, knm[h] = max_k ||k_h||  (Cauchy-Schwarz softmax shift)
__global__ void norms_kernel(const float* __restrict__ Q, const float* __restrict__ K,
                             float* qn, float* knm) {
    int i = blockIdx.x * blockDim.x + threadIdx.x;
    if (i >= NN * 2) return;
    int q = i >> 1, h = i & 1;
    const float* qp = Q + (size_t)q * 64 + h * 32;
    const float* kp = K + (size_t)q * 64 + h * 32;
    float sq = 0.f, sk = 0.f;
#pragma unroll
    for (int c = 0; c < 32; c++) { sq = fmaf(qp[c], qp[c], sq); sk = fmaf(kp[c], kp[c], sk); }
    qn[i] = sqrtf(sq);
    atomicMaxF(&knm[h], sqrtf(sk));
}

// E[h][q][k] = exp(scale*(q.k - ||q||*knm)) stored fp16; accumulates row sums dsum[q*2+h] in fp32.
__global__ __launch_bounds__(256) void qk_exp_kernel(const float* __restrict__ Q,
                                                     const float* __restrict__ Kmat,
                                                     const float* __restrict__ qn,
                                                     const float* __restrict__ knm,
                                                     __half* __restrict__ S,
                                                     float* __restrict__ dsum) {
    __shared__ float Qs[128][33];
    __shared__ float Kt[32][132];
    int h = blockIdx.z;
    int q0 = blockIdx.y * 128, k0 = blockIdx.x * 128;
    int tid = threadIdx.x, tx = tid & 15, ty = tid >> 4;
#pragma unroll
    for (int i = 0; i < 4; i++) {
        int idx = tid + i * 256;
        int r = idx >> 3, c = (idx & 7) * 4;
        float4 v = *(const float4*)(Q + (size_t)(q0 + r) * 64 + h * 32 + c);
        Qs[r][c] = v.x; Qs[r][c + 1] = v.y; Qs[r][c + 2] = v.z; Qs[r][c + 3] = v.w;
        float4 kv = *(const float4*)(Kmat + (size_t)(k0 + r) * 64 + h * 32 + c);
        Kt[c][r] = kv.x; Kt[c + 1][r] = kv.y; Kt[c + 2][r] = kv.z; Kt[c + 3][r] = kv.w;
    }
    __syncthreads();
    unsigned long long acc2[8][4] = {};
#pragma unroll
    for (int c = 0; c < 32; c++) {
        unsigned long long av[8];
#pragma unroll
        for (int i = 0; i < 8; i++) PACK2(av[i], Qs[ty * 8 + i][c]);
        ulonglong2 bb0 = *(ulonglong2*)&Kt[c][tx * 8];
        ulonglong2 bb1 = *(ulonglong2*)&Kt[c][tx * 8 + 4];
        unsigned long long bv[4] = {bb0.x, bb0.y, bb1.x, bb1.y};
#pragma unroll
        for (int i = 0; i < 8; i++)
#pragma unroll
            for (int j = 0; j < 4; j++) FMA2(acc2[i][j], av[i], bv[j]);
    }
    const float scale = 0.17677669529663687f;  // 1/sqrt(32)
    float knmh = knm[h];
    __half* Sp = S + (size_t)h * NN * NN;
#pragma unroll
    for (int i = 0; i < 8; i++) {
        int q = q0 + ty * 8 + i;
        float shift = qn[q * 2 + h] * knmh;
        __half2 hv[4];
        float rs = 0.f;
#pragma unroll
        for (int j = 0; j < 4; j++) {
            unsigned int lo, hi;
            UNPACK2(lo, hi, acc2[i][j]);
            float e0 = __expf((__uint_as_float(lo) - shift) * scale);
            float e1 = __expf((__uint_as_float(hi) - shift) * scale);
            hv[j] = __floats2half2_rn(e0, e1);
            rs += e0 + e1;
        }
        size_t base = (size_t)q * NN + k0 + tx * 8;
        __stcs((float4*)(Sp + base), *(float4*)hv);
#pragma unroll
        for (int off = 8; off > 0; off >>= 1) rs += __shfl_down_sync(0xffffffffu, rs, off, 16);
        if (tx == 0) atomicAdd(&dsum[q * 2 + h], rs);
    }
}

// out[q, h*32+d] = sum_k (E[h][q][k]/dsum) * V[k][h*32+d]; writes head-averaged weights (fp32).
__global__ __launch_bounds__(256) void av_avg_kernel(const __half* __restrict__ Sh,
                                                     const float* __restrict__ V,
                                                     const float* __restrict__ dsum,
                                                     float* __restrict__ out,
                                                     float* __restrict__ avg) {
    __shared__ float P0s[32][65];
    __shared__ float P1s[32][65];
    __shared__ float Vs[32][64];
    __shared__ float invd0s[64], invd1s[64];
    int q0 = blockIdx.x * 64;
    int kbase = blockIdx.y * (NN / 4);
    int tid = threadIdx.x, tx = tid & 15, ty = tid >> 4;
    if (tid < 64) invd0s[tid] = 1.0f / dsum[(q0 + tid) * 2];
    else if (tid < 128) invd1s[tid - 64] = 1.0f / dsum[(q0 + tid - 64) * 2 + 1];
    __syncthreads();
    unsigned long long acc2[4][2] = {};
    const float* Ph = (tx < 8) ? &P0s[0][0] : &P1s[0][0];
    int pr = tid >> 2, pkc = (tid & 3) * 8;   // P-load role: row 0..63, k chunk of 8
    for (int kb = 0; kb < NN / 4; kb += 32) {
        {
            size_t goff = (size_t)(q0 + pr) * NN + kbase + kb + pkc;
            uint4 r0 = __ldcs((const uint4*)(Sh + goff));
            uint4 r1 = __ldcs((const uint4*)(Sh + (size_t)NN * NN + goff));
            float i0 = invd0s[pr], i1 = invd1s[pr];
            __half2* a0 = (__half2*)&r0;
            __half2* a1 = (__half2*)&r1;
            float p0[8], p1[8], av[8];
#pragma unroll
            for (int j = 0; j < 4; j++) {
                float2 f0 = __half22float2(a0[j]);
                float2 f1 = __half22float2(a1[j]);
                p0[2 * j] = f0.x * i0; p0[2 * j + 1] = f0.y * i0;
                p1[2 * j] = f1.x * i1; p1[2 * j + 1] = f1.y * i1;
            }
#pragma unroll
            for (int t = 0; t < 8; t++) {
                av[t] = 0.5f * (p0[t] + p1[t]);
                P0s[pkc + t][pr] = p0[t];
                P1s[pkc + t][pr] = p1[t];
            }
            float4 w0 = {av[0], av[1], av[2], av[3]};
            float4 w1 = {av[4], av[5], av[6], av[7]};
            __stcs((float4*)(avg + goff), w0);
            __stcs((float4*)(avg + goff + 4), w1);
        }
#pragma unroll
        for (int i = 0; i < 2; i++) {
            int idx = tid + i * 256;
            int kr = idx >> 4, c = (idx & 15) * 4;
            *(float4*)&Vs[kr][c] = *(const float4*)(V + (size_t)(kbase + kb + kr) * 64 + c);
        }
        __syncthreads();
#pragma unroll
        for (int kk = 0; kk < 32; kk++) {
            const float* Pp = Ph + kk * 65;
            ulonglong2 bb = *(ulonglong2*)&Vs[kk][tx * 4];
#pragma unroll
            for (int i = 0; i < 4; i++) {
                unsigned long long a2;
                PACK2(a2, Pp[ty * 4 + i]);
                FMA2(acc2[i][0], a2, bb.x);
                FMA2(acc2[i][1], a2, bb.y);
            }
        }
        __syncthreads();
    }
#pragma unroll
    for (int i = 0; i < 4; i++) {
#pragma unroll
        for (int j = 0; j < 2; j++) {
            unsigned int lo, hi;
            UNPACK2(lo, hi, acc2[i][j]);
            atomicAdd(&out[(size_t)(q0 + ty * 4 + i) * 64 + tx * 4 + 2 * j], __uint_as_float(lo));
            atomicAdd(&out[(size_t)(q0 + ty * 4 + i) * 64 + tx * 4 + 2 * j + 1], __uint_as_float(hi));
        }
    }
}

// ---------------- misc tail ----------------
__global__ void concat_kernel(const float* __restrict__ a, const float* __restrict__ b,
                              float* __restrict__ o) {
    int i = blockIdx.x * blockDim.x + threadIdx.x;
    if (i >= NN * 128) return;
    int n = i >> 7, c = i & 127;
    o[i] = (c < 64) ? a[n * 64 + c] : b[n * 64 + c - 64];
}

__global__ void fc2_kernel(const float* __restrict__ t, const float* __restrict__ W,
                           const float* __restrict__ b, float* __restrict__ pred) {
    int w = (blockIdx.x * blockDim.x + threadIdx.x) >> 5;
    int lane = threadIdx.x & 31;
    if (w >= NN) return;
    float s = t[(size_t)w * 64 + lane] * W[lane] + t[(size_t)w * 64 + lane + 32] * W[lane + 32];
#pragma unroll
    for (int off = 16; off > 0; off >>= 1) s += __shfl_down_sync(0xffffffffu, s, off);
    if (lane == 0) pred[w] = s + b[0];
}

// ---------------- launch ----------------
extern "C" void kernel_launch(void* const* d_in, const int* in_sizes, int n_in,
                              void* d_out, int out_size) {
    const float* x       = (const float*)d_in[0];
    const int*   eit     = (const int*)d_in[1];
    const int*   eie     = (const int*)d_in[2];
    const float* gat1_W  = (const float*)d_in[3];
    const float* gat1_as = (const float*)d_in[4];
    const float* gat1_ad = (const float*)d_in[5];
    const float* gat1_b  = (const float*)d_in[6];
    const float* gat2_W  = (const float*)d_in[7];
    const float* gat2_as = (const float*)d_in[8];
    const float* gat2_ad = (const float*)d_in[9];
    const float* gat2_b  = (const float*)d_in[10];
    const float* gcn1_W  = (const float*)d_in[11];
    const float* gcn1_b  = (const float*)d_in[12];
    const float* gcn2_W  = (const float*)d_in[13];
    const float* gcn2_b  = (const float*)d_in[14];
    const float* Wq = (const float*)d_in[15]; const float* bq = (const float*)d_in[16];
    const float* Wk = (const float*)d_in[17]; const float* bk = (const float*)d_in[18];
    const float* Wv = (const float*)d_in[19]; const float* bv = (const float*)d_in[20];
    const float* Wo = (const float*)d_in[21]; const float* bo = (const float*)d_in[22];
    const float* fc1_W = (const float*)d_in[23]; const float* fc1_b = (const float*)d_in[24];
    const float* fc2_W = (const float*)d_in[25]; const float* fc2_b = (const float*)d_in[26];

    float* out_pred = (float*)d_out;
    float* out_attn = (float*)d_out + NN;

    __half* pS;
    float *ph1, *pagg1, *pht1, *ph2, *pagg2, *phtkg;
    float *pas1, *pad1, *pm1, *pd1, *pe1, *pas2, *pad2, *pm2, *pd2, *pe2;
    float *pdeg, *pdinv, *pg1, *page1, *phe1, *pg2, *page2, *phekg;
    float *pq, *pk, *pv, *pao, *phat, *pfus, *pt1, *pqn, *pknm, *pdsum;
    cudaGetSymbolAddress((void**)&pS, g_S);
    cudaGetSymbolAddress((void**)&ph1, g_h1);     cudaGetSymbolAddress((void**)&pagg1, g_agg1);
    cudaGetSymbolAddress((void**)&pht1, g_ht1);   cudaGetSymbolAddress((void**)&ph2, g_h2);
    cudaGetSymbolAddress((void**)&pagg2, g_agg2); cudaGetSymbolAddress((void**)&phtkg, g_htkg);
    cudaGetSymbolAddress((void**)&pas1, g_as1);   cudaGetSymbolAddress((void**)&pad1, g_ad1);
    cudaGetSymbolAddress((void**)&pm1, g_m1);     cudaGetSymbolAddress((void**)&pd1, g_d1);
    cudaGetSymbolAddress((void**)&pe1, g_eexp1);
    cudaGetSymbolAddress((void**)&pas2, g_as2);   cudaGetSymbolAddress((void**)&pad2, g_ad2);
    cudaGetSymbolAddress((void**)&pm2, g_m2);     cudaGetSymbolAddress((void**)&pd2, g_d2);
    cudaGetSymbolAddress((void**)&pe2, g_eexp2);
    cudaGetSymbolAddress((void**)&pdeg, g_deg);   cudaGetSymbolAddress((void**)&pdinv, g_dinv);
    cudaGetSymbolAddress((void**)&pg1, g_g1);     cudaGetSymbolAddress((void**)&page1, g_agge1);
    cudaGetSymbolAddress((void**)&phe1, g_he1);   cudaGetSymbolAddress((void**)&pg2, g_g2);
    cudaGetSymbolAddress((void**)&page2, g_agge2);cudaGetSymbolAddress((void**)&phekg, g_hekg);
    cudaGetSymbolAddress((void**)&pq, g_q);       cudaGetSymbolAddress((void**)&pk, g_k);
    cudaGetSymbolAddress((void**)&pv, g_v);       cudaGetSymbolAddress((void**)&pao, g_attnout);
    cudaGetSymbolAddress((void**)&phat, g_hattn); cudaGetSymbolAddress((void**)&pfus, g_fused);
    cudaGetSymbolAddress((void**)&pt1, g_t1);
    cudaGetSymbolAddress((void**)&pqn, g_qn);     cudaGetSymbolAddress((void**)&pknm, g_knm);
    cudaGetSymbolAddress((void**)&pdsum, g_dsum);

    const int T = 256;
    const int EB = (ETOT + T - 1) / T;

    // ===== GAT layer 1 (heads=2, concat) =====
    gemm64<<<dim3(2, 128), 256>>>(x, gat1_W, nullptr, ph1, NN, 128, DIN, 0);
    gat_alpha_coef<<<(NN * 2 + T - 1) / T, T>>>(ph1, gat1_as, gat1_ad, pas1, pad1, 2);
    fill_kernel<<<(NN * 2 + T - 1) / T, T>>>(pm1, -INFINITY, NN * 2);
    cudaMemsetAsync(pd1, 0, NN * 2 * sizeof(float));
    cudaMemsetAsync(pagg1, 0, (size_t)NN * 128 * sizeof(float));
    gat_edge_max<<<EB, T>>>(eit, pas1, pad1, pm1, 2);
    gat_edge_exp<<<EB, T>>>(eit, pas1, pad1, pm1, pd1, pe1, 2);
    gat_edge_aggr<<<(ETOT * 2 * 32 + T - 1) / T, T>>>(eit, ph1, pe1, pd1, pagg1, 2);
    bias_act_kernel<<<(NN * 128 + T - 1) / T, T>>>(pagg1, gat1_b, pht1, NN, 128, 2);

    // ===== GAT layer 2 (heads=1, mean) =====
    gemm64<<<dim3(1, 128), 256>>>(pht1, gat2_W, nullptr, ph2, NN, 64, 128, 0);
    gat_alpha_coef<<<(NN + T - 1) / T, T>>>(ph2, gat2_as, gat2_ad, pas2, pad2, 1);
    fill_kernel<<<(NN + T - 1) / T, T>>>(pm2, -INFINITY, NN);
    cudaMemsetAsync(pd2, 0, NN * sizeof(float));
    cudaMemsetAsync(pagg2, 0, (size_t)NN * 64 * sizeof(float));
    gat_edge_max<<<EB, T>>>(eit, pas2, pad2, pm2, 1);
    gat_edge_exp<<<EB, T>>>(eit, pas2, pad2, pm2, pd2, pe2, 1);
    gat_edge_aggr<<<(ETOT * 32 + T - 1) / T, T>>>(eit, ph2, pe2, pd2, pagg2, 1);
    bias_act_kernel<<<(NN * 64 + T - 1) / T, T>>>(pagg2, gat2_b, phtkg, NN, 64, 2);

    // ===== GCN branch =====
    cudaMemsetAsync(pdeg, 0, NN * sizeof(float));
    deg_kernel<<<EB, T>>>(eie, pdeg);
    dinv_kernel<<<(NN + T - 1) / T, T>>>(pdeg, pdinv);
    gemm64<<<dim3(1, 128), 256>>>(x, gcn1_W, nullptr, pg1, NN, 64, DIN, 0);
    cudaMemsetAsync(page1, 0, (size_t)NN * 64 * sizeof(float));
    gcn_aggr<<<(ETOT * 32 + T - 1) / T, T>>>(eie, pg1, pdinv, page1);
    bias_act_kernel<<<(NN * 64 + T - 1) / T, T>>>(page1, gcn1_b, phe1, NN, 64, 1);
    gemm64<<<dim3(1, 128), 256>>>(phe1, gcn2_W, nullptr, pg2, NN, 64, 64, 0);
    cudaMemsetAsync(page2, 0, (size_t)NN * 64 * sizeof(float));
    gcn_aggr<<<(ETOT * 32 + T - 1) / T, T>>>(eie, pg2, pdinv, page2);
    bias_act_kernel<<<(NN * 64 + T - 1) / T, T>>>(page2, gcn2_b, phekg, NN, 64, 1);

    // ===== cross attention (fused softmax via Cauchy-Schwarz shift, fp16 S) =====
    gemm64<<<dim3(1, 128), 256>>>(phtkg, Wq, bq, pq, NN, 64, 64, 0);
    gemm64<<<dim3(1, 128), 256>>>(phekg, Wk, bk, pk, NN, 64, 64, 0);
    gemm64<<<dim3(1, 128), 256>>>(phekg, Wv, bv, pv, NN, 64, 64, 0);
    cudaMemsetAsync(pknm, 0, 2 * sizeof(float));
    cudaMemsetAsync(pdsum, 0, NN * 2 * sizeof(float));
    norms_kernel<<<(NN * 2 + T - 1) / T, T>>>(pq, pk, pqn, pknm);
    qk_exp_kernel<<<dim3(64, 64, 2), 256>>>(pq, pk, pqn, pknm, pS, pdsum);
    cudaMemsetAsync(pao, 0, (size_t)NN * 64 * sizeof(float));
    av_avg_kernel<<<dim3(128, 4), 256>>>(pS, pv, pdsum, pao, out_attn);
    gemm64<<<dim3(1, 128), 256>>>(pao, Wo, bo, phat, NN, 64, 64, 0);

    // ===== head =====
    concat_kernel<<<(NN * 128 + T - 1) / T, T>>>(phtkg, phat, pfus);
    gemm64<<<dim3(1, 128), 256>>>(pfus, fc1_W, fc1_b, pt1, NN, 64, 128, 1);
    fc2_kernel<<<(NN * 32 + T - 1) / T, T>>>(pt1, fc2_W, fc2_b, out_pred);
}

// round 4
// speedup vs baseline: 1.6516x; 1.4231x over previous
#include <cuda_runtime.h>
#include <cuda_fp16.h>
#include <mma.h>
#include <math.h>

using namespace nvcuda;

#define NN 8192
#define EE 262144
#define ETOT (EE + NN)
#define DIN 256
#define HID 64

// ---------------- scratch (device globals; no allocation allowed) ----------------
static __device__ __half g_S[(size_t)2 * NN * NN];         // 268 MB: per-head unnormalized exp scores (fp16)
static __device__ float g_h1[NN * 128];
static __device__ float g_agg1[NN * 128];
static __device__ float g_ht1[NN * 128];
static __device__ float g_h2[NN * 64];
static __device__ float g_agg2[NN * 64];
static __device__ float g_htkg[NN * 64];
static __device__ float g_as1[NN * 2], g_ad1[NN * 2], g_m1[NN * 2], g_d1[NN * 2];
static __device__ float g_eexp1[ETOT * 2];
static __device__ float g_as2[NN], g_ad2[NN], g_m2[NN], g_d2[NN];
static __device__ float g_eexp2[ETOT];
static __device__ float g_deg[NN], g_dinv[NN];
static __device__ float g_g1[NN * 64], g_agge1[NN * 64], g_he1[NN * 64];
static __device__ float g_g2[NN * 64], g_agge2[NN * 64], g_hekg[NN * 64];
static __device__ float g_q[NN * 64], g_k[NN * 64], g_v[NN * 64];
static __device__ __half g_qh[NN * 64], g_kh[NN * 64], g_vh[NN * 64];
static __device__ float g_attnout[NN * 64];
static __device__ float g_hattn[NN * 64];
static __device__ float g_fused[NN * 128];
static __device__ float g_t1[NN * 64];
static __device__ float g_qn[NN * 2];      // per (q,head) L2 norm of q
static __device__ float g_knm[2];          // per head max_k ||k||
static __device__ float g_dsum[NN * 2];    // per (q,head) softmax denominator

// ---------------- helpers ----------------
__device__ __forceinline__ void atomicMaxF(float* addr, float v) {
    if (v >= 0.f) atomicMax((int*)addr, __float_as_int(v));
    else          atomicMin((unsigned int*)addr, __float_as_uint(v));
}

__global__ void fill_kernel(float* p, float v, int n) {
    int i = blockIdx.x * blockDim.x + threadIdx.x;
    if (i < n) p[i] = v;
}

__global__ void f2h_kernel(const float* __restrict__ a, __half* __restrict__ b, int n) {
    int i = blockIdx.x * blockDim.x + threadIdx.x;
    if (i * 2 + 1 < n) {
        float2 v = *(const float2*)(a + i * 2);
        *(__half2*)(b + i * 2) = __floats2half2_rn(v.x, v.y);
    }
}

// ---------------- generic tiled GEMM: C = act(A[M,K] @ B[K,N] + bias) ----------------
__global__ __launch_bounds__(256) void gemm64(const float* __restrict__ A,
                                              const float* __restrict__ B,
                                              const float* __restrict__ bias,
                                              float* __restrict__ C,
                                              int M, int N, int K, int act) {
    __shared__ float As[16][65];
    __shared__ float Bs[16][64];
    int tid = threadIdx.x;
    int tx = tid & 15, ty = tid >> 4;
    int m0 = blockIdx.y * 64, n0 = blockIdx.x * 64;
    float acc[4][4] = {};
    for (int k0 = 0; k0 < K; k0 += 16) {
        {
            int r = tid >> 2, c = (tid & 3) * 4;
            float4 av = *(const float4*)(A + (size_t)(m0 + r) * K + k0 + c);
            As[c + 0][r] = av.x; As[c + 1][r] = av.y; As[c + 2][r] = av.z; As[c + 3][r] = av.w;
        }
        {
            int r = tid >> 4, c = (tid & 15) * 4;
            float4 bv = *(const float4*)(B + (size_t)(k0 + r) * N + n0 + c);
            *(float4*)&Bs[r][c] = bv;
        }
        __syncthreads();
#pragma unroll
        for (int kk = 0; kk < 16; kk++) {
            float a[4], b[4];
#pragma unroll
            for (int i = 0; i < 4; i++) a[i] = As[kk][ty * 4 + i];
            float4 bv = *(float4*)&Bs[kk][tx * 4];
            b[0] = bv.x; b[1] = bv.y; b[2] = bv.z; b[3] = bv.w;
#pragma unroll
            for (int i = 0; i < 4; i++)
#pragma unroll
                for (int j = 0; j < 4; j++) acc[i][j] = fmaf(a[i], b[j], acc[i][j]);
        }
        __syncthreads();
    }
#pragma unroll
    for (int i = 0; i < 4; i++) {
        int m = m0 + ty * 4 + i;
#pragma unroll
        for (int j = 0; j < 4; j++) {
            int n = n0 + tx * 4 + j;
            float v = acc[i][j];
            if (bias) v += bias[n];
            if (act == 1) v = fmaxf(v, 0.f);
            else if (act == 2) v = (v > 0.f) ? v : expm1f(v);
            C[(size_t)m * N + n] = v;
        }
    }
}

// ---------------- GAT attention coefficients ----------------
__global__ void gat_alpha_coef(const float* __restrict__ h, const float* __restrict__ att_src,
                               const float* __restrict__ att_dst, float* as_, float* ad_, int H) {
    int i = blockIdx.x * blockDim.x + threadIdx.x;
    if (i >= NN * H) return;
    int n = i / H, hh = i % H;
    const float* hp = h + (size_t)n * H * HID + hh * HID;
    const float* s = att_src + hh * HID;
    const float* d = att_dst + hh * HID;
    float ss = 0.f, dd = 0.f;
#pragma unroll 8
    for (int c = 0; c < HID; c++) { ss = fmaf(hp[c], s[c], ss); dd = fmaf(hp[c], d[c], dd); }
    as_[i] = ss; ad_[i] = dd;
}

__global__ void gat_edge_max(const int* __restrict__ ei, const float* __restrict__ as_,
                             const float* __restrict__ ad_, float* m, int H) {
    int e = blockIdx.x * blockDim.x + threadIdx.x;
    if (e >= ETOT) return;
    int s = (e < EE) ? ei[e] : (e - EE);
    int d = (e < EE) ? ei[EE + e] : (e - EE);
    for (int h = 0; h < H; h++) {
        float x = as_[s * H + h] + ad_[d * H + h];
        x = (x >= 0.f) ? x : 0.2f * x;
        atomicMaxF(&m[d * H + h], x);
    }
}

__global__ void gat_edge_exp(const int* __restrict__ ei, const float* __restrict__ as_,
                             const float* __restrict__ ad_, const float* __restrict__ m,
                             float* denom, float* eexp, int H) {
    int e = blockIdx.x * blockDim.x + threadIdx.x;
    if (e >= ETOT) return;
    int s = (e < EE) ? ei[e] : (e - EE);
    int d = (e < EE) ? ei[EE + e] : (e - EE);
    for (int h = 0; h < H; h++) {
        float x = as_[s * H + h] + ad_[d * H + h];
        x = (x >= 0.f) ? x : 0.2f * x;
        float ex = expf(x - m[d * H + h]);
        eexp[e * H + h] = ex;
        atomicAdd(&denom[d * H + h], ex);
    }
}

// one warp per (edge, head); HID=64 -> 2 floats per lane
__global__ void gat_edge_aggr(const int* __restrict__ ei, const float* __restrict__ h,
                              const float* __restrict__ eexp, const float* __restrict__ denom,
                              float* out, int H) {
    int w = (blockIdx.x * blockDim.x + threadIdx.x) >> 5;
    int lane = threadIdx.x & 31;
    if (w >= ETOT * H) return;
    int e = w / H, hh = w - e * H;
    int s = (e < EE) ? ei[e] : (e - EE);
    int d = (e < EE) ? ei[EE + e] : (e - EE);
    float alpha = eexp[e * H + hh] / (denom[d * H + hh] + 1e-16f);
    const float* hs = h + (size_t)s * H * HID + hh * HID;
    float* od = out + (size_t)d * H * HID + hh * HID;
    atomicAdd(&od[lane], alpha * hs[lane]);
    atomicAdd(&od[lane + 32], alpha * hs[lane + 32]);
}

__global__ void bias_act_kernel(const float* __restrict__ in, const float* __restrict__ bias,
                                float* out, int M, int N, int act) {
    int i = blockIdx.x * blockDim.x + threadIdx.x;
    if (i >= M * N) return;
    int n = i % N;
    float v = in[i] + bias[n];
    if (act == 1) v = fmaxf(v, 0.f);
    else if (act == 2) v = (v > 0.f) ? v : expm1f(v);
    out[i] = v;
}

// ---------------- GCN ----------------
__global__ void deg_kernel(const int* __restrict__ ei, float* deg) {
    int e = blockIdx.x * blockDim.x + threadIdx.x;
    if (e >= ETOT) return;
    int d = (e < EE) ? ei[EE + e] : (e - EE);
    atomicAdd(&deg[d], 1.0f);
}

__global__ void dinv_kernel(const float* deg, float* dinv) {
    int i = blockIdx.x * blockDim.x + threadIdx.x;
    if (i < NN) dinv[i] = rsqrtf(fmaxf(deg[i], 1.0f));
}

__global__ void gcn_aggr(const int* __restrict__ ei, const float* __restrict__ hg,
                         const float* __restrict__ dinv, float* out) {
    int w = (blockIdx.x * blockDim.x + threadIdx.x) >> 5;
    int lane = threadIdx.x & 31;
    if (w >= ETOT) return;
    int s = (w < EE) ? ei[w] : (w - EE);
    int d = (w < EE) ? ei[EE + w] : (w - EE);
    float nrm = dinv[s] * dinv[d];
    const float* hs = hg + (size_t)s * 64;
    float* od = out + (size_t)d * 64;
    atomicAdd(&od[lane], nrm * hs[lane]);
    atomicAdd(&od[lane + 32], nrm * hs[lane + 32]);
}

// ---------------- attention ----------------
// norms: qn[q*2+h] = ||q_h||, knm[h] = max_k ||k_h||  (Cauchy-Schwarz softmax shift)
__global__ void norms_kernel(const float* __restrict__ Q, const float* __restrict__ K,
                             float* qn, float* knm) {
    int i = blockIdx.x * blockDim.x + threadIdx.x;
    if (i >= NN * 2) return;
    int q = i >> 1, h = i & 1;
    const float* qp = Q + (size_t)q * 64 + h * 32;
    const float* kp = K + (size_t)q * 64 + h * 32;
    float sq = 0.f, sk = 0.f;
#pragma unroll
    for (int c = 0; c < 32; c++) { sq = fmaf(qp[c], qp[c], sq); sk = fmaf(kp[c], kp[c], sk); }
    qn[i] = sqrtf(sq);
    atomicMaxF(&knm[h], sqrtf(sk));
}

// E[h][q][k] = exp(scale*(q.k - ||q||*knm)) via HMMA; fp16 store; fp32 row sums -> dsum.
// Block tile: 64 q x 128 k. 8 warps = 2(q) x 4(k), each 32x32 via wmma 16x16x16.
__global__ __launch_bounds__(256) void qk_exp_wmma(const __half* __restrict__ Qh,
                                                   const __half* __restrict__ Kh,
                                                   const float* __restrict__ qn,
                                                   const float* __restrict__ knm,
                                                   __half* __restrict__ S,
                                                   float* __restrict__ dsum) {
    __shared__ __align__(32) char buf[36864];
    __half* Qs = (__half*)buf;                 // [64][40]
    __half* Ks = (__half*)(buf + 5120);        // [128][40]
    float* stage = (float*)buf;                // overlay after sync: [8][32*36]
    int h = blockIdx.z;
    int q0 = blockIdx.y * 64, k0 = blockIdx.x * 128;
    int tid = threadIdx.x, wid = tid >> 5, lane = tid & 31;
    {
        int r = tid >> 2, c8 = (tid & 3) * 8;  // 64 rows x 4 chunks
        *(uint4*)&Qs[r * 40 + c8] = *(const uint4*)(Qh + (size_t)(q0 + r) * 64 + h * 32 + c8);
    }
#pragma unroll
    for (int i = 0; i < 2; i++) {
        int idx = tid + i * 256;
        int r = idx >> 2, c8 = (idx & 3) * 8;  // 128 rows x 4 chunks
        *(uint4*)&Ks[r * 40 + c8] = *(const uint4*)(Kh + (size_t)(k0 + r) * 64 + h * 32 + c8);
    }
    __syncthreads();
    int qsub = (wid >> 2) * 32, ksub = (wid & 3) * 32;
    wmma::fragment<wmma::accumulator, 16, 16, 16, float> acc[2][2];
#pragma unroll
    for (int mi = 0; mi < 2; mi++)
#pragma unroll
        for (int ni = 0; ni < 2; ni++) wmma::fill_fragment(acc[mi][ni], 0.0f);
#pragma unroll
    for (int ks = 0; ks < 2; ks++) {
        wmma::fragment<wmma::matrix_a, 16, 16, 16, __half, wmma::row_major> a[2];
        wmma::fragment<wmma::matrix_b, 16, 16, 16, __half, wmma::col_major> b[2];
#pragma unroll
        for (int mi = 0; mi < 2; mi++)
            wmma::load_matrix_sync(a[mi], &Qs[(qsub + mi * 16) * 40 + ks * 16], 40);
#pragma unroll
        for (int ni = 0; ni < 2; ni++)
            wmma::load_matrix_sync(b[ni], &Ks[(ksub + ni * 16) * 40 + ks * 16], 40);
#pragma unroll
        for (int mi = 0; mi < 2; mi++)
#pragma unroll
            for (int ni = 0; ni < 2; ni++)
                wmma::mma_sync(acc[mi][ni], a[mi], b[ni], acc[mi][ni]);
    }
    __syncthreads();   // everyone done reading Qs/Ks; overlay stage
    float* wst = stage + wid * (32 * 36);
#pragma unroll
    for (int mi = 0; mi < 2; mi++)
#pragma unroll
        for (int ni = 0; ni < 2; ni++)
            wmma::store_matrix_sync(&wst[mi * 16 * 36 + ni * 16], acc[mi][ni], 36, wmma::mem_row_major);
    // one lane per q-row: exp + row sum + store
    const float sc = 0.17677669529663687f;   // 1/sqrt(32)
    int q = q0 + qsub + lane;
    float shift = qn[q * 2 + h] * knm[h];
    const float* sp = &wst[lane * 36];
    float rs = 0.f;
    __half2 hv[16];
#pragma unroll
    for (int j = 0; j < 16; j++) {
        float e0 = __expf((sp[2 * j] - shift) * sc);
        float e1 = __expf((sp[2 * j + 1] - shift) * sc);
        hv[j] = __floats2half2_rn(e0, e1);
        rs += e0 + e1;
    }
    __half* Sp = S + (size_t)h * NN * NN + (size_t)q * NN + k0 + ksub;
#pragma unroll
    for (int t = 0; t < 4; t++) __stcs((uint4*)(Sp + t * 8), *(uint4*)&hv[t * 4]);
    atomicAdd(&dsum[q * 2 + h], rs);
}

// out[q, h*32+c] += sum_k E[h][q][k] * V[k][h*32+c] (unnormalized; scaled later).
// Also streams head-averaged normalized weights. Block: 128 q x 64 cols, k-split 4.
__global__ __launch_bounds__(256) void av_wmma(const __half* __restrict__ Sh,
                                               const __half* __restrict__ Vh,
                                               const float* __restrict__ dsum,
                                               float* __restrict__ out,
                                               float* __restrict__ avg) {
    __shared__ __align__(32) char buf[36864];
    __half* E0s = (__half*)buf;                // [128][40]
    __half* E1s = (__half*)(buf + 10240);      // [128][40]
    __half* Vs  = (__half*)(buf + 20480);      // [32][72]
    float* stage = (float*)buf;                // overlay at end: [8][32*36]
    __shared__ float invd[256];
    int q0 = blockIdx.x * 128;
    int kbase = blockIdx.y * 2048;
    int tid = threadIdx.x, wid = tid >> 5, lane = tid & 31;
    if (tid < 128) invd[tid] = 1.0f / dsum[(q0 + tid) * 2];
    else           invd[tid] = 1.0f / dsum[(q0 + tid - 128) * 2 + 1];
    int hh = wid >> 2, qsub = (wid & 3) * 32;
    wmma::fragment<wmma::accumulator, 16, 16, 16, float> acc[2][2];
#pragma unroll
    for (int mi = 0; mi < 2; mi++)
#pragma unroll
        for (int ni = 0; ni < 2; ni++) wmma::fill_fragment(acc[mi][ni], 0.0f);
    for (int kc = 0; kc < 2048; kc += 32) {
        __syncthreads();   // protect smem from previous iteration's readers
#pragma unroll
        for (int i = 0; i < 2; i++) {
            int idx = tid + i * 256;
            int r = idx >> 2, c8 = (idx & 3) * 8;   // 128 rows x 4 chunks of 8
            size_t goff = (size_t)(q0 + r) * NN + kbase + kc + c8;
            uint4 u0 = __ldcs((const uint4*)(Sh + goff));
            uint4 u1 = __ldcs((const uint4*)(Sh + (size_t)NN * NN + goff));
            *(uint4*)&E0s[r * 40 + c8] = u0;
            *(uint4*)&E1s[r * 40 + c8] = u1;
            float i0 = invd[r], i1 = invd[128 + r];
            __half2* a0 = (__half2*)&u0;
            __half2* a1 = (__half2*)&u1;
            float av8[8];
#pragma unroll
            for (int j = 0; j < 4; j++) {
                float2 f0 = __half22float2(a0[j]);
                float2 f1 = __half22float2(a1[j]);
                av8[2 * j]     = 0.5f * (f0.x * i0 + f1.x * i1);
                av8[2 * j + 1] = 0.5f * (f0.y * i0 + f1.y * i1);
            }
            __stcs((float4*)(avg + goff), *(float4*)&av8[0]);
            __stcs((float4*)(avg + goff + 4), *(float4*)&av8[4]);
        }
        {
            int r = tid >> 3, c8 = (tid & 7) * 8;   // 32 rows x 8 chunks of 8
            *(uint4*)&Vs[r * 72 + c8] = *(const uint4*)(Vh + (size_t)(kbase + kc + r) * 64 + c8);
        }
        __syncthreads();
        __half* Es = hh ? E1s : E0s;
#pragma unroll
        for (int ks = 0; ks < 2; ks++) {
            wmma::fragment<wmma::matrix_a, 16, 16, 16, __half, wmma::row_major> a[2];
            wmma::fragment<wmma::matrix_b, 16, 16, 16, __half, wmma::row_major> b[2];
#pragma unroll
            for (int mi = 0; mi < 2; mi++)
                wmma::load_matrix_sync(a[mi], &Es[(qsub + mi * 16) * 40 + ks * 16], 40);
#pragma unroll
            for (int ni = 0; ni < 2; ni++)
                wmma::load_matrix_sync(b[ni], &Vs[(ks * 16) * 72 + hh * 32 + ni * 16], 72);
#pragma unroll
            for (int mi = 0; mi < 2; mi++)
#pragma unroll
                for (int ni = 0; ni < 2; ni++)
                    wmma::mma_sync(acc[mi][ni], a[mi], b[ni], acc[mi][ni]);
        }
    }
    __syncthreads();
    float* wst = stage + wid * (32 * 36);
#pragma unroll
    for (int mi = 0; mi < 2; mi++)
#pragma unroll
        for (int ni = 0; ni < 2; ni++)
            wmma::store_matrix_sync(&wst[mi * 16 * 36 + ni * 16], acc[mi][ni], 36, wmma::mem_row_major);
    int q = q0 + qsub + lane;
    const float* sp = &wst[lane * 36];
#pragma unroll
    for (int j = 0; j < 32; j++)
        atomicAdd(&out[(size_t)q * 64 + hh * 32 + j], sp[j]);
}

__global__ void scale_out_kernel(float* __restrict__ out, const float* __restrict__ dsum) {
    int i = blockIdx.x * blockDim.x + threadIdx.x;
    if (i >= NN * 64) return;
    int q = i >> 6, h = (i >> 5) & 1;
    out[i] *= 1.0f / dsum[q * 2 + h];
}

// ---------------- misc tail ----------------
__global__ void concat_kernel(const float* __restrict__ a, const float* __restrict__ b,
                              float* __restrict__ o) {
    int i = blockIdx.x * blockDim.x + threadIdx.x;
    if (i >= NN * 128) return;
    int n = i >> 7, c = i & 127;
    o[i] = (c < 64) ? a[n * 64 + c] : b[n * 64 + c - 64];
}

__global__ void fc2_kernel(const float* __restrict__ t, const float* __restrict__ W,
                           const float* __restrict__ b, float* __restrict__ pred) {
    int w = (blockIdx.x * blockDim.x + threadIdx.x) >> 5;
    int lane = threadIdx.x & 31;
    if (w >= NN) return;
    float s = t[(size_t)w * 64 + lane] * W[lane] + t[(size_t)w * 64 + lane + 32] * W[lane + 32];
#pragma unroll
    for (int off = 16; off > 0; off >>= 1) s += __shfl_down_sync(0xffffffffu, s, off);
    if (lane == 0) pred[w] = s + b[0];
}

// ---------------- launch ----------------
extern "C" void kernel_launch(void* const* d_in, const int* in_sizes, int n_in,
                              void* d_out, int out_size) {
    const float* x       = (const float*)d_in[0];
    const int*   eit     = (const int*)d_in[1];
    const int*   eie     = (const int*)d_in[2];
    const float* gat1_W  = (const float*)d_in[3];
    const float* gat1_as = (const float*)d_in[4];
    const float* gat1_ad = (const float*)d_in[5];
    const float* gat1_b  = (const float*)d_in[6];
    const float* gat2_W  = (const float*)d_in[7];
    const float* gat2_as = (const float*)d_in[8];
    const float* gat2_ad = (const float*)d_in[9];
    const float* gat2_b  = (const float*)d_in[10];
    const float* gcn1_W  = (const float*)d_in[11];
    const float* gcn1_b  = (const float*)d_in[12];
    const float* gcn2_W  = (const float*)d_in[13];
    const float* gcn2_b  = (const float*)d_in[14];
    const float* Wq = (const float*)d_in[15]; const float* bq = (const float*)d_in[16];
    const float* Wk = (const float*)d_in[17]; const float* bk = (const float*)d_in[18];
    const float* Wv = (const float*)d_in[19]; const float* bv = (const float*)d_in[20];
    const float* Wo = (const float*)d_in[21]; const float* bo = (const float*)d_in[22];
    const float* fc1_W = (const float*)d_in[23]; const float* fc1_b = (const float*)d_in[24];
    const float* fc2_W = (const float*)d_in[25]; const float* fc2_b = (const float*)d_in[26];

    float* out_pred = (float*)d_out;
    float* out_attn = (float*)d_out + NN;

    __half *pS, *pqh, *pkh, *pvh;
    float *ph1, *pagg1, *pht1, *ph2, *pagg2, *phtkg;
    float *pas1, *pad1, *pm1, *pd1, *pe1, *pas2, *pad2, *pm2, *pd2, *pe2;
    float *pdeg, *pdinv, *pg1, *page1, *phe1, *pg2, *page2, *phekg;
    float *pq, *pk, *pv, *pao, *phat, *pfus, *pt1, *pqn, *pknm, *pdsum;
    cudaGetSymbolAddress((void**)&pS, g_S);
    cudaGetSymbolAddress((void**)&pqh, g_qh);    cudaGetSymbolAddress((void**)&pkh, g_kh);
    cudaGetSymbolAddress((void**)&pvh, g_vh);
    cudaGetSymbolAddress((void**)&ph1, g_h1);     cudaGetSymbolAddress((void**)&pagg1, g_agg1);
    cudaGetSymbolAddress((void**)&pht1, g_ht1);   cudaGetSymbolAddress((void**)&ph2, g_h2);
    cudaGetSymbolAddress((void**)&pagg2, g_agg2); cudaGetSymbolAddress((void**)&phtkg, g_htkg);
    cudaGetSymbolAddress((void**)&pas1, g_as1);   cudaGetSymbolAddress((void**)&pad1, g_ad1);
    cudaGetSymbolAddress((void**)&pm1, g_m1);     cudaGetSymbolAddress((void**)&pd1, g_d1);
    cudaGetSymbolAddress((void**)&pe1, g_eexp1);
    cudaGetSymbolAddress((void**)&pas2, g_as2);   cudaGetSymbolAddress((void**)&pad2, g_ad2);
    cudaGetSymbolAddress((void**)&pm2, g_m2);     cudaGetSymbolAddress((void**)&pd2, g_d2);
    cudaGetSymbolAddress((void**)&pe2, g_eexp2);
    cudaGetSymbolAddress((void**)&pdeg, g_deg);   cudaGetSymbolAddress((void**)&pdinv, g_dinv);
    cudaGetSymbolAddress((void**)&pg1, g_g1);     cudaGetSymbolAddress((void**)&page1, g_agge1);
    cudaGetSymbolAddress((void**)&phe1, g_he1);   cudaGetSymbolAddress((void**)&pg2, g_g2);
    cudaGetSymbolAddress((void**)&page2, g_agge2);cudaGetSymbolAddress((void**)&phekg, g_hekg);
    cudaGetSymbolAddress((void**)&pq, g_q);       cudaGetSymbolAddress((void**)&pk, g_k);
    cudaGetSymbolAddress((void**)&pv, g_v);       cudaGetSymbolAddress((void**)&pao, g_attnout);
    cudaGetSymbolAddress((void**)&phat, g_hattn); cudaGetSymbolAddress((void**)&pfus, g_fused);
    cudaGetSymbolAddress((void**)&pt1, g_t1);
    cudaGetSymbolAddress((void**)&pqn, g_qn);     cudaGetSymbolAddress((void**)&pknm, g_knm);
    cudaGetSymbolAddress((void**)&pdsum, g_dsum);

    const int T = 256;
    const int EB = (ETOT + T - 1) / T;

    // ===== GAT layer 1 (heads=2, concat) =====
    gemm64<<<dim3(2, 128), 256>>>(x, gat1_W, nullptr, ph1, NN, 128, DIN, 0);
    gat_alpha_coef<<<(NN * 2 + T - 1) / T, T>>>(ph1, gat1_as, gat1_ad, pas1, pad1, 2);
    fill_kernel<<<(NN * 2 + T - 1) / T, T>>>(pm1, -INFINITY, NN * 2);
    cudaMemsetAsync(pd1, 0, NN * 2 * sizeof(float));
    cudaMemsetAsync(pagg1, 0, (size_t)NN * 128 * sizeof(float));
    gat_edge_max<<<EB, T>>>(eit, pas1, pad1, pm1, 2);
    gat_edge_exp<<<EB, T>>>(eit, pas1, pad1, pm1, pd1, pe1, 2);
    gat_edge_aggr<<<(ETOT * 2 * 32 + T - 1) / T, T>>>(eit, ph1, pe1, pd1, pagg1, 2);
    bias_act_kernel<<<(NN * 128 + T - 1) / T, T>>>(pagg1, gat1_b, pht1, NN, 128, 2);

    // ===== GAT layer 2 (heads=1, mean) =====
    gemm64<<<dim3(1, 128), 256>>>(pht1, gat2_W, nullptr, ph2, NN, 64, 128, 0);
    gat_alpha_coef<<<(NN + T - 1) / T, T>>>(ph2, gat2_as, gat2_ad, pas2, pad2, 1);
    fill_kernel<<<(NN + T - 1) / T, T>>>(pm2, -INFINITY, NN);
    cudaMemsetAsync(pd2, 0, NN * sizeof(float));
    cudaMemsetAsync(pagg2, 0, (size_t)NN * 64 * sizeof(float));
    gat_edge_max<<<EB, T>>>(eit, pas2, pad2, pm2, 1);
    gat_edge_exp<<<EB, T>>>(eit, pas2, pad2, pm2, pd2, pe2, 1);
    gat_edge_aggr<<<(ETOT * 32 + T - 1) / T, T>>>(eit, ph2, pe2, pd2, pagg2, 1);
    bias_act_kernel<<<(NN * 64 + T - 1) / T, T>>>(pagg2, gat2_b, phtkg, NN, 64, 2);

    // ===== GCN branch =====
    cudaMemsetAsync(pdeg, 0, NN * sizeof(float));
    deg_kernel<<<EB, T>>>(eie, pdeg);
    dinv_kernel<<<(NN + T - 1) / T, T>>>(pdeg, pdinv);
    gemm64<<<dim3(1, 128), 256>>>(x, gcn1_W, nullptr, pg1, NN, 64, DIN, 0);
    cudaMemsetAsync(page1, 0, (size_t)NN * 64 * sizeof(float));
    gcn_aggr<<<(ETOT * 32 + T - 1) / T, T>>>(eie, pg1, pdinv, page1);
    bias_act_kernel<<<(NN * 64 + T - 1) / T, T>>>(page1, gcn1_b, phe1, NN, 64, 1);
    gemm64<<<dim3(1, 128), 256>>>(phe1, gcn2_W, nullptr, pg2, NN, 64, 64, 0);
    cudaMemsetAsync(page2, 0, (size_t)NN * 64 * sizeof(float));
    gcn_aggr<<<(ETOT * 32 + T - 1) / T, T>>>(eie, pg2, pdinv, page2);
    bias_act_kernel<<<(NN * 64 + T - 1) / T, T>>>(page2, gcn2_b, phekg, NN, 64, 1);

    // ===== cross attention (HMMA + fused softmax via Cauchy-Schwarz shift, fp16 S) =====
    gemm64<<<dim3(1, 128), 256>>>(phtkg, Wq, bq, pq, NN, 64, 64, 0);
    gemm64<<<dim3(1, 128), 256>>>(phekg, Wk, bk, pk, NN, 64, 64, 0);
    gemm64<<<dim3(1, 128), 256>>>(phekg, Wv, bv, pv, NN, 64, 64, 0);
    f2h_kernel<<<(NN * 32 + T - 1) / T, T>>>(pq, pqh, NN * 64);
    f2h_kernel<<<(NN * 32 + T - 1) / T, T>>>(pk, pkh, NN * 64);
    f2h_kernel<<<(NN * 32 + T - 1) / T, T>>>(pv, pvh, NN * 64);
    cudaMemsetAsync(pknm, 0, 2 * sizeof(float));
    cudaMemsetAsync(pdsum, 0, NN * 2 * sizeof(float));
    norms_kernel<<<(NN * 2 + T - 1) / T, T>>>(pq, pk, pqn, pknm);
    qk_exp_wmma<<<dim3(64, 128, 2), 256>>>(pqh, pkh, pqn, pknm, pS, pdsum);
    cudaMemsetAsync(pao, 0, (size_t)NN * 64 * sizeof(float));
    av_wmma<<<dim3(64, 4), 256>>>(pS, pvh, pdsum, pao, out_attn);
    scale_out_kernel<<<(NN * 64 + T - 1) / T, T>>>(pao, pdsum);
    gemm64<<<dim3(1, 128), 256>>>(pao, Wo, bo, phat, NN, 64, 64, 0);

    // ===== head =====
    concat_kernel<<<(NN * 128 + T - 1) / T, T>>>(phtkg, phat, pfus);
    gemm64<<<dim3(1, 128), 256>>>(pfus, fc1_W, fc1_b, pt1, NN, 64, 128, 1);
    fc2_kernel<<<(NN * 32 + T - 1) / T, T>>>(pt1, fc2_W, fc2_b, out_pred);
}

// round 5
// speedup vs baseline: 1.9771x; 1.1970x over previous
#include <cuda_runtime.h>
#include <cuda_fp16.h>
#include <mma.h>
#include <math.h>

using namespace nvcuda;

#define NN 8192
#define EE 262144
#define DIN 256
#define HID 64

// ---------------- scratch (device globals; no allocation allowed) ----------------
static __device__ __half g_S[(size_t)2 * NN * NN];         // 268 MB: per-head unnormalized exp scores (fp16)
static __device__ float g_h1[NN * 128];
static __device__ float g_ht1[NN * 128];
static __device__ float g_h2[NN * 64];
static __device__ float g_htkg[NN * 64];
static __device__ float g_as1[NN * 2], g_ad1[NN * 2];
static __device__ float g_as2[NN], g_ad2[NN];
static __device__ float g_dinv[NN];
static __device__ float g_g1[NN * 64], g_he1[NN * 64];
static __device__ float g_g2[NN * 64], g_hekg[NN * 64];
static __device__ float g_q[NN * 64], g_k[NN * 64], g_v[NN * 64];
static __device__ __half g_qh[NN * 64], g_kh[NN * 64], g_vh[NN * 64];
static __device__ float g_attnout[NN * 64];
static __device__ float g_hattn[NN * 64];
static __device__ float g_fused[NN * 128];
static __device__ float g_t1[NN * 64];
static __device__ float g_qn[NN * 2];      // per (q,head) L2 norm of q
static __device__ float g_knm[2];          // per head max_k ||k||
static __device__ float g_dsum[NN * 2];    // per (q,head) softmax denominator
// CSR scratch (two graphs)
static __device__ int g_cnt_t[NN], g_cur_t[NN], g_off_t[NN + 1], g_srcs_t[EE];
static __device__ int g_cnt_e[NN], g_cur_e[NN], g_off_e[NN + 1], g_srcs_e[EE];

// ---------------- helpers ----------------
__device__ __forceinline__ void atomicMaxF(float* addr, float v) {
    if (v >= 0.f) atomicMax((int*)addr, __float_as_int(v));
    else          atomicMin((unsigned int*)addr, __float_as_uint(v));
}

__device__ __forceinline__ float leaky(float x) { return (x >= 0.f) ? x : 0.2f * x; }

// ---------------- CSR build ----------------
__global__ void hist_kernel(const int* __restrict__ ei, int* cnt) {
    int e = blockIdx.x * blockDim.x + threadIdx.x;
    if (e < EE) atomicAdd(&cnt[ei[EE + e]], 1);
}

__global__ __launch_bounds__(1024) void scan_kernel(const int* __restrict__ cnt, int* __restrict__ off) {
    __shared__ int sm[1024];
    int tid = threadIdx.x;
    int base = tid * 8;
    int local[8];
    int s = 0;
#pragma unroll
    for (int j = 0; j < 8; j++) { local[j] = s; s += cnt[base + j]; }
    sm[tid] = s;
    __syncthreads();
    for (int d = 1; d < 1024; d <<= 1) {
        int v = (tid >= d) ? sm[tid - d] : 0;
        __syncthreads();
        sm[tid] += v;
        __syncthreads();
    }
    int pre = (tid == 0) ? 0 : sm[tid - 1];
#pragma unroll
    for (int j = 0; j < 8; j++) off[base + j] = pre + local[j];
    if (tid == 1023) off[NN] = sm[1023];
}

__global__ void scatter_kernel(const int* __restrict__ ei, const int* __restrict__ off,
                               int* cur, int* __restrict__ srcs) {
    int e = blockIdx.x * blockDim.x + threadIdx.x;
    if (e >= EE) return;
    int d = ei[EE + e];
    int p = off[d] + atomicAdd(&cur[d], 1);
    srcs[p] = ei[e];
}

__global__ void dinv_kernel(const int* __restrict__ cnt, float* dinv) {
    int i = blockIdx.x * blockDim.x + threadIdx.x;
    if (i < NN) dinv[i] = rsqrtf((float)(cnt[i] + 1));
}

// ---------------- generic tiled GEMM: C = act(A[M,K] @ B[K,N] + bias); optional fp16 copy ----------------
__global__ __launch_bounds__(256) void gemm64(const float* __restrict__ A,
                                              const float* __restrict__ B,
                                              const float* __restrict__ bias,
                                              float* __restrict__ C,
                                              __half* __restrict__ Ch,
                                              int M, int N, int K, int act) {
    __shared__ float As[16][65];
    __shared__ float Bs[16][64];
    int tid = threadIdx.x;
    int tx = tid & 15, ty = tid >> 4;
    int m0 = blockIdx.y * 64, n0 = blockIdx.x * 64;
    float acc[4][4] = {};
    for (int k0 = 0; k0 < K; k0 += 16) {
        {
            int r = tid >> 2, c = (tid & 3) * 4;
            float4 av = *(const float4*)(A + (size_t)(m0 + r) * K + k0 + c);
            As[c + 0][r] = av.x; As[c + 1][r] = av.y; As[c + 2][r] = av.z; As[c + 3][r] = av.w;
        }
        {
            int r = tid >> 4, c = (tid & 15) * 4;
            float4 bv = *(const float4*)(B + (size_t)(k0 + r) * N + n0 + c);
            *(float4*)&Bs[r][c] = bv;
        }
        __syncthreads();
#pragma unroll
        for (int kk = 0; kk < 16; kk++) {
            float a[4], b[4];
#pragma unroll
            for (int i = 0; i < 4; i++) a[i] = As[kk][ty * 4 + i];
            float4 bv = *(float4*)&Bs[kk][tx * 4];
            b[0] = bv.x; b[1] = bv.y; b[2] = bv.z; b[3] = bv.w;
#pragma unroll
            for (int i = 0; i < 4; i++)
#pragma unroll
                for (int j = 0; j < 4; j++) acc[i][j] = fmaf(a[i], b[j], acc[i][j]);
        }
        __syncthreads();
    }
#pragma unroll
    for (int i = 0; i < 4; i++) {
        int m = m0 + ty * 4 + i;
#pragma unroll
        for (int j = 0; j < 4; j++) {
            int n = n0 + tx * 4 + j;
            float v = acc[i][j];
            if (bias) v += bias[n];
            if (act == 1) v = fmaxf(v, 0.f);
            else if (act == 2) v = (v > 0.f) ? v : expm1f(v);
            C[(size_t)m * N + n] = v;
            if (Ch) Ch[(size_t)m * N + n] = __float2half(v);
        }
    }
}

// ---------------- GAT ----------------
__global__ void gat_alpha_coef(const float* __restrict__ h, const float* __restrict__ att_src,
                               const float* __restrict__ att_dst, float* as_, float* ad_, int H) {
    int i = blockIdx.x * blockDim.x + threadIdx.x;
    if (i >= NN * H) return;
    int n = i / H, hh = i % H;
    const float* hp = h + (size_t)n * H * HID + hh * HID;
    const float* s = att_src + hh * HID;
    const float* d = att_dst + hh * HID;
    float ss = 0.f, dd = 0.f;
#pragma unroll 8
    for (int c = 0; c < HID; c++) { ss = fmaf(hp[c], s[c], ss); dd = fmaf(hp[c], d[c], dd); }
    as_[i] = ss; ad_[i] = dd;
}

// one warp per (dst, head): CSR gather, softmax in registers, fused bias+ELU.
__global__ void gat_aggr_csr(const int* __restrict__ off, const int* __restrict__ srcs,
                             const float* __restrict__ as_, const float* __restrict__ ad_,
                             const float* __restrict__ hfeat, const float* __restrict__ bias,
                             float* __restrict__ out, int H) {
    int w = (blockIdx.x * blockDim.x + threadIdx.x) >> 5;
    int lane = threadIdx.x & 31;
    if (w >= NN * H) return;
    int d = w / H, hh = w - d * H;
    int beg = off[d], end = off[d + 1];
    float adv = ad_[w];
    float selfx = leaky(as_[w] + adv);
    // pass 1: row max
    float m = selfx;
    for (int i = beg + lane; i < end; i += 32)
        m = fmaxf(m, leaky(__ldg(&as_[srcs[i] * H + hh]) + adv));
#pragma unroll
    for (int o = 16; o > 0; o >>= 1) m = fmaxf(m, __shfl_xor_sync(0xffffffffu, m, o));
    // pass 2: sum of exp
    float ssum = (lane == 0) ? __expf(selfx - m) : 0.f;
    for (int i = beg + lane; i < end; i += 32)
        ssum += __expf(leaky(__ldg(&as_[srcs[i] * H + hh]) + adv) - m);
#pragma unroll
    for (int o = 16; o > 0; o >>= 1) ssum += __shfl_xor_sync(0xffffffffu, ssum, o);
    float inv = 1.0f / (ssum + 1e-16f);
    // pass 3: weighted feature gather (sequential edges, coalesced features)
    int stride = H * HID;
    int fo = hh * HID;
    float alf = __expf(selfx - m) * inv;
    float a0 = alf * hfeat[(size_t)d * stride + fo + lane];
    float a1 = alf * hfeat[(size_t)d * stride + fo + lane + 32];
    for (int i = beg; i < end; i++) {
        int s = srcs[i];
        float xx = leaky(__ldg(&as_[s * H + hh]) + adv);
        float al = __expf(xx - m) * inv;
        const float* hs = hfeat + (size_t)s * stride + fo;
        a0 = fmaf(al, hs[lane], a0);
        a1 = fmaf(al, hs[lane + 32], a1);
    }
    float v0 = a0 + bias[fo + lane];
    float v1 = a1 + bias[fo + lane + 32];
    v0 = (v0 > 0.f) ? v0 : expm1f(v0);   // ELU
    v1 = (v1 > 0.f) ? v1 : expm1f(v1);
    out[(size_t)d * stride + fo + lane] = v0;
    out[(size_t)d * stride + fo + lane + 32] = v1;
}

// ---------------- GCN: one warp per dst, CSR gather, fused bias+ReLU ----------------
__global__ void gcn_aggr_csr(const int* __restrict__ off, const int* __restrict__ srcs,
                             const float* __restrict__ hg, const float* __restrict__ dinv,
                             const float* __restrict__ bias, float* __restrict__ out) {
    int w = (blockIdx.x * blockDim.x + threadIdx.x) >> 5;
    int lane = threadIdx.x & 31;
    if (w >= NN) return;
    int d = w;
    int beg = off[d], end = off[d + 1];
    float dv = dinv[d];
    float a0 = dv * hg[(size_t)d * 64 + lane];
    float a1 = dv * hg[(size_t)d * 64 + lane + 32];
    for (int i = beg; i < end; i++) {
        int s = srcs[i];
        float ds = __ldg(&dinv[s]);
        const float* hs = hg + (size_t)s * 64;
        a0 = fmaf(ds, hs[lane], a0);
        a1 = fmaf(ds, hs[lane + 32], a1);
    }
    float v0 = fmaf(dv, a0, bias[lane]);
    float v1 = fmaf(dv, a1, bias[lane + 32]);
    out[(size_t)d * 64 + lane] = fmaxf(v0, 0.f);
    out[(size_t)d * 64 + lane + 32] = fmaxf(v1, 0.f);
}

// ---------------- attention ----------------
__global__ void norms_kernel(const float* __restrict__ Q, const float* __restrict__ K,
                             float* qn, float* knm) {
    int i = blockIdx.x * blockDim.x + threadIdx.x;
    if (i >= NN * 2) return;
    int q = i >> 1, h = i & 1;
    const float* qp = Q + (size_t)q * 64 + h * 32;
    const float* kp = K + (size_t)q * 64 + h * 32;
    float sq = 0.f, sk = 0.f;
#pragma unroll
    for (int c = 0; c < 32; c++) { sq = fmaf(qp[c], qp[c], sq); sk = fmaf(kp[c], kp[c], sk); }
    qn[i] = sqrtf(sq);
    atomicMaxF(&knm[h], sqrtf(sk));
}

// E[h][q][k] = exp(scale*(q.k - ||q||*knm)) via HMMA; fp16 store; fp32 row sums -> dsum.
__global__ __launch_bounds__(256) void qk_exp_wmma(const __half* __restrict__ Qh,
                                                   const __half* __restrict__ Kh,
                                                   const float* __restrict__ qn,
                                                   const float* __restrict__ knm,
                                                   __half* __restrict__ S,
                                                   float* __restrict__ dsum) {
    __shared__ __align__(32) char buf[36864];
    __half* Qs = (__half*)buf;                 // [64][40]
    __half* Ks = (__half*)(buf + 5120);        // [128][40]
    float* stage = (float*)buf;                // overlay after sync: [8][32*36]
    int h = blockIdx.z;
    int q0 = blockIdx.y * 64, k0 = blockIdx.x * 128;
    int tid = threadIdx.x, wid = tid >> 5, lane = tid & 31;
    {
        int r = tid >> 2, c8 = (tid & 3) * 8;
        *(uint4*)&Qs[r * 40 + c8] = *(const uint4*)(Qh + (size_t)(q0 + r) * 64 + h * 32 + c8);
    }
#pragma unroll
    for (int i = 0; i < 2; i++) {
        int idx = tid + i * 256;
        int r = idx >> 2, c8 = (idx & 3) * 8;
        *(uint4*)&Ks[r * 40 + c8] = *(const uint4*)(Kh + (size_t)(k0 + r) * 64 + h * 32 + c8);
    }
    __syncthreads();
    int qsub = (wid >> 2) * 32, ksub = (wid & 3) * 32;
    wmma::fragment<wmma::accumulator, 16, 16, 16, float> acc[2][2];
#pragma unroll
    for (int mi = 0; mi < 2; mi++)
#pragma unroll
        for (int ni = 0; ni < 2; ni++) wmma::fill_fragment(acc[mi][ni], 0.0f);
#pragma unroll
    for (int ks = 0; ks < 2; ks++) {
        wmma::fragment<wmma::matrix_a, 16, 16, 16, __half, wmma::row_major> a[2];
        wmma::fragment<wmma::matrix_b, 16, 16, 16, __half, wmma::col_major> b[2];
#pragma unroll
        for (int mi = 0; mi < 2; mi++)
            wmma::load_matrix_sync(a[mi], &Qs[(qsub + mi * 16) * 40 + ks * 16], 40);
#pragma unroll
        for (int ni = 0; ni < 2; ni++)
            wmma::load_matrix_sync(b[ni], &Ks[(ksub + ni * 16) * 40 + ks * 16], 40);
#pragma unroll
        for (int mi = 0; mi < 2; mi++)
#pragma unroll
            for (int ni = 0; ni < 2; ni++)
                wmma::mma_sync(acc[mi][ni], a[mi], b[ni], acc[mi][ni]);
    }
    __syncthreads();
    float* wst = stage + wid * (32 * 36);
#pragma unroll
    for (int mi = 0; mi < 2; mi++)
#pragma unroll
        for (int ni = 0; ni < 2; ni++)
            wmma::store_matrix_sync(&wst[mi * 16 * 36 + ni * 16], acc[mi][ni], 36, wmma::mem_row_major);
    const float sc = 0.17677669529663687f;   // 1/sqrt(32)
    int q = q0 + qsub + lane;
    float shiftsc = qn[q * 2 + h] * knm[h] * sc;
    const float* sp = &wst[lane * 36];
    float rs = 0.f;
    __half2 hv[16];
#pragma unroll
    for (int j = 0; j < 16; j++) {
        float e0 = __expf(fmaf(sp[2 * j], sc, -shiftsc));
        float e1 = __expf(fmaf(sp[2 * j + 1], sc, -shiftsc));
        hv[j] = __floats2half2_rn(e0, e1);
        rs += e0 + e1;
    }
    __half* Sp = S + (size_t)h * NN * NN + (size_t)q * NN + k0 + ksub;
#pragma unroll
    for (int t = 0; t < 4; t++) __stcs((uint4*)(Sp + t * 8), *(uint4*)&hv[t * 4]);
    atomicAdd(&dsum[q * 2 + h], rs);
}

// out[q, h*32+c] += sum_k E[h][q][k] * V[k][h*32+c]; streams head-averaged normalized weights.
__global__ __launch_bounds__(256) void av_wmma(const __half* __restrict__ Sh,
                                               const __half* __restrict__ Vh,
                                               const float* __restrict__ dsum,
                                               float* __restrict__ out,
                                               float* __restrict__ avg) {
    __shared__ __align__(32) char buf[36864];
    __half* E0s = (__half*)buf;                // [128][40]
    __half* E1s = (__half*)(buf + 10240);      // [128][40]
    __half* Vs  = (__half*)(buf + 20480);      // [32][72]
    float* stage = (float*)buf;                // overlay at end: [8][32*36]
    __shared__ float invd[256];
    int q0 = blockIdx.x * 128;
    int kbase = blockIdx.y * 2048;
    int tid = threadIdx.x, wid = tid >> 5, lane = tid & 31;
    if (tid < 128) invd[tid] = 1.0f / dsum[(q0 + tid) * 2];
    else           invd[tid] = 1.0f / dsum[(q0 + tid - 128) * 2 + 1];
    int hh = wid >> 2, qsub = (wid & 3) * 32;
    wmma::fragment<wmma::accumulator, 16, 16, 16, float> acc[2][2];
#pragma unroll
    for (int mi = 0; mi < 2; mi++)
#pragma unroll
        for (int ni = 0; ni < 2; ni++) wmma::fill_fragment(acc[mi][ni], 0.0f);
    for (int kc = 0; kc < 2048; kc += 32) {
        __syncthreads();
#pragma unroll
        for (int i = 0; i < 2; i++) {
            int idx = tid + i * 256;
            int r = idx >> 2, c8 = (idx & 3) * 8;
            size_t goff = (size_t)(q0 + r) * NN + kbase + kc + c8;
            uint4 u0 = __ldcs((const uint4*)(Sh + goff));
            uint4 u1 = __ldcs((const uint4*)(Sh + (size_t)NN * NN + goff));
            *(uint4*)&E0s[r * 40 + c8] = u0;
            *(uint4*)&E1s[r * 40 + c8] = u1;
            float i0 = invd[r], i1 = invd[128 + r];
            __half2* a0 = (__half2*)&u0;
            __half2* a1 = (__half2*)&u1;
            float av8[8];
#pragma unroll
            for (int j = 0; j < 4; j++) {
                float2 f0 = __half22float2(a0[j]);
                float2 f1 = __half22float2(a1[j]);
                av8[2 * j]     = 0.5f * (f0.x * i0 + f1.x * i1);
                av8[2 * j + 1] = 0.5f * (f0.y * i0 + f1.y * i1);
            }
            __stcs((float4*)(avg + goff), *(float4*)&av8[0]);
            __stcs((float4*)(avg + goff + 4), *(float4*)&av8[4]);
        }
        {
            int r = tid >> 3, c8 = (tid & 7) * 8;
            *(uint4*)&Vs[r * 72 + c8] = *(const uint4*)(Vh + (size_t)(kbase + kc + r) * 64 + c8);
        }
        __syncthreads();
        __half* Es = hh ? E1s : E0s;
#pragma unroll
        for (int ks = 0; ks < 2; ks++) {
            wmma::fragment<wmma::matrix_a, 16, 16, 16, __half, wmma::row_major> a[2];
            wmma::fragment<wmma::matrix_b, 16, 16, 16, __half, wmma::row_major> b[2];
#pragma unroll
            for (int mi = 0; mi < 2; mi++)
                wmma::load_matrix_sync(a[mi], &Es[(qsub + mi * 16) * 40 + ks * 16], 40);
#pragma unroll
            for (int ni = 0; ni < 2; ni++)
                wmma::load_matrix_sync(b[ni], &Vs[(ks * 16) * 72 + hh * 32 + ni * 16], 72);
#pragma unroll
            for (int mi = 0; mi < 2; mi++)
#pragma unroll
                for (int ni = 0; ni < 2; ni++)
                    wmma::mma_sync(acc[mi][ni], a[mi], b[ni], acc[mi][ni]);
        }
    }
    __syncthreads();
    float* wst = stage + wid * (32 * 36);
#pragma unroll
    for (int mi = 0; mi < 2; mi++)
#pragma unroll
        for (int ni = 0; ni < 2; ni++)
            wmma::store_matrix_sync(&wst[mi * 16 * 36 + ni * 16], acc[mi][ni], 36, wmma::mem_row_major);
    int q = q0 + qsub + lane;
    const float* sp = &wst[lane * 36];
#pragma unroll
    for (int j = 0; j < 32; j++)
        atomicAdd(&out[(size_t)q * 64 + hh * 32 + j], sp[j]);
}

__global__ void scale_out_kernel(float* __restrict__ out, const float* __restrict__ dsum) {
    int i = blockIdx.x * blockDim.x + threadIdx.x;
    if (i >= NN * 64) return;
    int q = i >> 6, h = (i >> 5) & 1;
    out[i] *= 1.0f / dsum[q * 2 + h];
}

// ---------------- misc tail ----------------
__global__ void concat_kernel(const float* __restrict__ a, const float* __restrict__ b,
                              float* __restrict__ o) {
    int i = blockIdx.x * blockDim.x + threadIdx.x;
    if (i >= NN * 128) return;
    int n = i >> 7, c = i & 127;
    o[i] = (c < 64) ? a[n * 64 + c] : b[n * 64 + c - 64];
}

__global__ void fc2_kernel(const float* __restrict__ t, const float* __restrict__ W,
                           const float* __restrict__ b, float* __restrict__ pred) {
    int w = (blockIdx.x * blockDim.x + threadIdx.x) >> 5;
    int lane = threadIdx.x & 31;
    if (w >= NN) return;
    float s = t[(size_t)w * 64 + lane] * W[lane] + t[(size_t)w * 64 + lane + 32] * W[lane + 32];
#pragma unroll
    for (int off = 16; off > 0; off >>= 1) s += __shfl_down_sync(0xffffffffu, s, off);
    if (lane == 0) pred[w] = s + b[0];
}

// ---------------- launch ----------------
extern "C" void kernel_launch(void* const* d_in, const int* in_sizes, int n_in,
                              void* d_out, int out_size) {
    const float* x       = (const float*)d_in[0];
    const int*   eit     = (const int*)d_in[1];
    const int*   eie     = (const int*)d_in[2];
    const float* gat1_W  = (const float*)d_in[3];
    const float* gat1_as = (const float*)d_in[4];
    const float* gat1_ad = (const float*)d_in[5];
    const float* gat1_b  = (const float*)d_in[6];
    const float* gat2_W  = (const float*)d_in[7];
    const float* gat2_as = (const float*)d_in[8];
    const float* gat2_ad = (const float*)d_in[9];
    const float* gat2_b  = (const float*)d_in[10];
    const float* gcn1_W  = (const float*)d_in[11];
    const float* gcn1_b  = (const float*)d_in[12];
    const float* gcn2_W  = (const float*)d_in[13];
    const float* gcn2_b  = (const float*)d_in[14];
    const float* Wq = (const float*)d_in[15]; const float* bq = (const float*)d_in[16];
    const float* Wk = (const float*)d_in[17]; const float* bk = (const float*)d_in[18];
    const float* Wv = (const float*)d_in[19]; const float* bv = (const float*)d_in[20];
    const float* Wo = (const float*)d_in[21]; const float* bo = (const float*)d_in[22];
    const float* fc1_W = (const float*)d_in[23]; const float* fc1_b = (const float*)d_in[24];
    const float* fc2_W = (const float*)d_in[25]; const float* fc2_b = (const float*)d_in[26];

    float* out_pred = (float*)d_out;
    float* out_attn = (float*)d_out + NN;

    __half *pS, *pqh, *pkh, *pvh;
    float *ph1, *pht1, *ph2, *phtkg, *pas1, *pad1, *pas2, *pad2;
    float *pdinv, *pg1, *phe1, *pg2, *phekg;
    float *pq, *pk, *pv, *pao, *phat, *pfus, *pt1, *pqn, *pknm, *pdsum;
    int *pcnt_t, *pcur_t, *poff_t, *psrcs_t, *pcnt_e, *pcur_e, *poff_e, *psrcs_e;
    cudaGetSymbolAddress((void**)&pS, g_S);
    cudaGetSymbolAddress((void**)&pqh, g_qh);    cudaGetSymbolAddress((void**)&pkh, g_kh);
    cudaGetSymbolAddress((void**)&pvh, g_vh);
    cudaGetSymbolAddress((void**)&ph1, g_h1);    cudaGetSymbolAddress((void**)&pht1, g_ht1);
    cudaGetSymbolAddress((void**)&ph2, g_h2);    cudaGetSymbolAddress((void**)&phtkg, g_htkg);
    cudaGetSymbolAddress((void**)&pas1, g_as1);  cudaGetSymbolAddress((void**)&pad1, g_ad1);
    cudaGetSymbolAddress((void**)&pas2, g_as2);  cudaGetSymbolAddress((void**)&pad2, g_ad2);
    cudaGetSymbolAddress((void**)&pdinv, g_dinv);
    cudaGetSymbolAddress((void**)&pg1, g_g1);    cudaGetSymbolAddress((void**)&phe1, g_he1);
    cudaGetSymbolAddress((void**)&pg2, g_g2);    cudaGetSymbolAddress((void**)&phekg, g_hekg);
    cudaGetSymbolAddress((void**)&pq, g_q);      cudaGetSymbolAddress((void**)&pk, g_k);
    cudaGetSymbolAddress((void**)&pv, g_v);      cudaGetSymbolAddress((void**)&pao, g_attnout);
    cudaGetSymbolAddress((void**)&phat, g_hattn);cudaGetSymbolAddress((void**)&pfus, g_fused);
    cudaGetSymbolAddress((void**)&pt1, g_t1);
    cudaGetSymbolAddress((void**)&pqn, g_qn);    cudaGetSymbolAddress((void**)&pknm, g_knm);
    cudaGetSymbolAddress((void**)&pdsum, g_dsum);
    cudaGetSymbolAddress((void**)&pcnt_t, g_cnt_t); cudaGetSymbolAddress((void**)&pcur_t, g_cur_t);
    cudaGetSymbolAddress((void**)&poff_t, g_off_t); cudaGetSymbolAddress((void**)&psrcs_t, g_srcs_t);
    cudaGetSymbolAddress((void**)&pcnt_e, g_cnt_e); cudaGetSymbolAddress((void**)&pcur_e, g_cur_e);
    cudaGetSymbolAddress((void**)&poff_e, g_off_e); cudaGetSymbolAddress((void**)&psrcs_e, g_srcs_e);

    const int T = 256;
    const int EB = (EE + T - 1) / T;

    // ===== CSR build (both graphs) =====
    cudaMemsetAsync(pcnt_t, 0, NN * sizeof(int));
    cudaMemsetAsync(pcur_t, 0, NN * sizeof(int));
    cudaMemsetAsync(pcnt_e, 0, NN * sizeof(int));
    cudaMemsetAsync(pcur_e, 0, NN * sizeof(int));
    hist_kernel<<<EB, T>>>(eit, pcnt_t);
    hist_kernel<<<EB, T>>>(eie, pcnt_e);
    scan_kernel<<<1, 1024>>>(pcnt_t, poff_t);
    scan_kernel<<<1, 1024>>>(pcnt_e, poff_e);
    scatter_kernel<<<EB, T>>>(eit, poff_t, pcur_t, psrcs_t);
    scatter_kernel<<<EB, T>>>(eie, poff_e, pcur_e, psrcs_e);
    dinv_kernel<<<(NN + T - 1) / T, T>>>(pcnt_e, pdinv);

    // ===== GAT layer 1 (heads=2, concat) =====
    gemm64<<<dim3(2, 128), 256>>>(x, gat1_W, nullptr, ph1, nullptr, NN, 128, DIN, 0);
    gat_alpha_coef<<<(NN * 2 + T - 1) / T, T>>>(ph1, gat1_as, gat1_ad, pas1, pad1, 2);
    gat_aggr_csr<<<(NN * 2 * 32 + T - 1) / T, T>>>(poff_t, psrcs_t, pas1, pad1, ph1, gat1_b, pht1, 2);

    // ===== GAT layer 2 (heads=1) =====
    gemm64<<<dim3(1, 128), 256>>>(pht1, gat2_W, nullptr, ph2, nullptr, NN, 64, 128, 0);
    gat_alpha_coef<<<(NN + T - 1) / T, T>>>(ph2, gat2_as, gat2_ad, pas2, pad2, 1);
    gat_aggr_csr<<<(NN * 32 + T - 1) / T, T>>>(poff_t, psrcs_t, pas2, pad2, ph2, gat2_b, phtkg, 1);

    // ===== GCN branch =====
    gemm64<<<dim3(1, 128), 256>>>(x, gcn1_W, nullptr, pg1, nullptr, NN, 64, DIN, 0);
    gcn_aggr_csr<<<(NN * 32 + T - 1) / T, T>>>(poff_e, psrcs_e, pg1, pdinv, gcn1_b, phe1);
    gemm64<<<dim3(1, 128), 256>>>(phe1, gcn2_W, nullptr, pg2, nullptr, NN, 64, 64, 0);
    gcn_aggr_csr<<<(NN * 32 + T - 1) / T, T>>>(poff_e, psrcs_e, pg2, pdinv, gcn2_b, phekg);

    // ===== cross attention (HMMA + fused softmax via Cauchy-Schwarz shift, fp16 S) =====
    gemm64<<<dim3(1, 128), 256>>>(phtkg, Wq, bq, pq, pqh, NN, 64, 64, 0);
    gemm64<<<dim3(1, 128), 256>>>(phekg, Wk, bk, pk, pkh, NN, 64, 64, 0);
    gemm64<<<dim3(1, 128), 256>>>(phekg, Wv, bv, pv, pvh, NN, 64, 64, 0);
    cudaMemsetAsync(pknm, 0, 2 * sizeof(float));
    cudaMemsetAsync(pdsum, 0, NN * 2 * sizeof(float));
    norms_kernel<<<(NN * 2 + T - 1) / T, T>>>(pq, pk, pqn, pknm);
    qk_exp_wmma<<<dim3(64, 128, 2), 256>>>(pqh, pkh, pqn, pknm, pS, pdsum);
    cudaMemsetAsync(pao, 0, (size_t)NN * 64 * sizeof(float));
    av_wmma<<<dim3(64, 4), 256>>>(pS, pvh, pdsum, pao, out_attn);
    scale_out_kernel<<<(NN * 64 + T - 1) / T, T>>>(pao, pdsum);
    gemm64<<<dim3(1, 128), 256>>>(pao, Wo, bo, phat, nullptr, NN, 64, 64, 0);

    // ===== head =====
    concat_kernel<<<(NN * 128 + T - 1) / T, T>>>(phtkg, phat, pfus);
    gemm64<<<dim3(1, 128), 256>>>(pfus, fc1_W, fc1_b, pt1, nullptr, NN, 64, 128, 1);
    fc2_kernel<<<(NN * 32 + T - 1) / T, T>>>(pt1, fc2_W, fc2_b, out_pred);
}